// round 6
// baseline (speedup 1.0000x reference)
#include <cuda_runtime.h>
#include <cstdint>

// Problem constants
#define D   1024
#define H   16
#define DH  64
#define FF  4096
#define SEQ 2048
#define MAXTOK 8192   // B=4 * S=2048

// ---------------- scratch (static device globals; no allocation) ----------------
__device__ float g_xln [MAXTOK * D];
__device__ float g_qkv [MAXTOK * 3 * D];
__device__ float g_attn[MAXTOK * D];
__device__ float g_res [MAXTOK * D];
__device__ float g_mln [MAXTOK * D];
__device__ float g_fc  [(size_t)MAXTOK * FF];
__device__ float g_wattn_t[3 * D * D];
__device__ float g_wproj_t[D * D];
__device__ float g_wfc_t  [FF * D];
__device__ float g_wmlp_t [D * FF];

// ---------------- helpers ----------------
__device__ __forceinline__ uint32_t smem_u32(const void* p){
    uint32_t a;
    asm("{ .reg .u64 t; cvta.to.shared.u64 t, %1; cvt.u32.u64 %0, t; }" : "=r"(a) : "l"(p));
    return a;
}
__device__ __forceinline__ float tf32r(float x){
    uint32_t u; asm("cvt.rna.tf32.f32 %0, %1;" : "=r"(u) : "f"(x));
    return __uint_as_float(u);
}
__device__ __forceinline__ void mma_tf32(float* c, const uint32_t* a, const uint32_t* b){
    asm volatile(
        "mma.sync.aligned.m16n8k8.row.col.f32.tf32.tf32.f32 "
        "{%0,%1,%2,%3}, {%4,%5,%6,%7}, {%8,%9}, {%0,%1,%2,%3};\n"
        : "+f"(c[0]), "+f"(c[1]), "+f"(c[2]), "+f"(c[3])
        : "r"(a[0]), "r"(a[1]), "r"(a[2]), "r"(a[3]), "r"(b[0]), "r"(b[1]));
}
__device__ __forceinline__ void cp16(uint32_t smem_addr, const void* gptr){
    asm volatile("cp.async.cg.shared.global [%0], [%1], 16;" :: "r"(smem_addr), "l"(gptr));
}

// ---------------- transpose: in[R][C] -> out[C][R], rounded to tf32 ----------------
__global__ __launch_bounds__(256) void transpose_kernel(const float* __restrict__ in,
                                                        float* __restrict__ out, int R, int C)
{
    __shared__ float t[32][33];
    int bx = blockIdx.x * 32, by = blockIdx.y * 32;
    int x = threadIdx.x & 31, y0 = threadIdx.x >> 5;
    #pragma unroll
    for (int yy = y0; yy < 32; yy += 8)
        t[yy][x] = in[(size_t)(by + yy) * C + bx + x];
    __syncthreads();
    #pragma unroll
    for (int yy = y0; yy < 32; yy += 8)
        out[(size_t)(bx + yy) * R + by + x] = tf32r(t[x][yy]);
}

// ---------------- LayerNorm (output rounded to tf32: feeds GEMM A) ----------------
__global__ __launch_bounds__(256) void ln_kernel(const float* __restrict__ in,
                                                 const float* __restrict__ gw,
                                                 const float* __restrict__ bw,
                                                 float* __restrict__ out)
{
    __shared__ float red0[8], red1[8];
    int row = blockIdx.x, tid = threadIdx.x;
    const float4* x4 = (const float4*)(in + (size_t)row * D);
    float4 v = x4[tid];
    float s  = v.x + v.y + v.z + v.w;
    float ss = v.x*v.x + v.y*v.y + v.z*v.z + v.w*v.w;
    #pragma unroll
    for (int o = 16; o; o >>= 1) {
        s  += __shfl_xor_sync(0xffffffffu, s,  o);
        ss += __shfl_xor_sync(0xffffffffu, ss, o);
    }
    if ((tid & 31) == 0) { red0[tid >> 5] = s; red1[tid >> 5] = ss; }
    __syncthreads();
    s = 0.f; ss = 0.f;
    #pragma unroll
    for (int i = 0; i < 8; i++) { s += red0[i]; ss += red1[i]; }
    float mean = s * (1.f / D);
    float var  = ss * (1.f / D) - mean * mean;
    float rstd = rsqrtf(var + 1e-5f);
    float4 gv = ((const float4*)gw)[tid];
    float4 bv = ((const float4*)bw)[tid];
    float4 o4;
    o4.x = tf32r((v.x - mean) * rstd * gv.x + bv.x);
    o4.y = tf32r((v.y - mean) * rstd * gv.y + bv.y);
    o4.z = tf32r((v.z - mean) * rstd * gv.z + bv.z);
    o4.w = tf32r((v.w - mean) * rstd * gv.w + bv.w);
    ((float4*)(out + (size_t)row * D))[tid] = o4;
}

// ============== mma.sync tf32 GEMM: C[M,N] = A[M,K] @ Bt[N,K]^T + epilogue ==============
// 3-stage cp.async pipeline, ONE __syncthreads per K-chunk.
#define BM 128
#define BN 128
#define BK 32
#define LDT 36
#define TBUF (128 * LDT)                 // floats per (A or B) per stage
#define NSTAGE 3
#define GSMEM (NSTAGE * 2 * TBUF * 4)    // 110592 B

template<int EPI>
__global__ __launch_bounds__(128) void tc_gemm(const float* __restrict__ A,
                                               const float* __restrict__ Bt,
                                               const float* __restrict__ bias,
                                               const float* __restrict__ res,
                                               float* __restrict__ C,
                                               int M, int N_, int K)
{
    extern __shared__ float smem[];
    const int tid = threadIdx.x, lane = tid & 31, wid = tid >> 5;
    const int wm = (wid >> 1) * 64, wn = (wid & 1) * 64;
    const int bm = blockIdx.y * BM, bn = blockIdx.x * BN;
    const int nch = K / BK;

    const float* Ag = A  + (size_t)bm * K;
    const float* Bg = Bt + (size_t)bn * K;

    float acc[4][8][4];
    #pragma unroll
    for (int mf = 0; mf < 4; mf++)
        #pragma unroll
        for (int nf = 0; nf < 8; nf++)
            #pragma unroll
            for (int q = 0; q < 4; q++) acc[mf][nf][q] = 0.f;

    // stage s: A at smem + s*2*TBUF, B at +TBUF
    auto load_chunk = [&](int c, int s) {
        float* dA = smem + s * 2 * TBUF;
        float* dB = dA + TBUF;
        const float* a0 = Ag + c * BK;
        const float* b0 = Bg + c * BK;
        #pragma unroll
        for (int i = 0; i < 8; i++) {
            int slot = i * 128 + tid;
            int r = slot >> 3, u = slot & 7;
            cp16(smem_u32(dA + r * LDT + u * 4), a0 + (size_t)r * K + u * 4);
            cp16(smem_u32(dB + r * LDT + u * 4), b0 + (size_t)r * K + u * 4);
        }
        asm volatile("cp.async.commit_group;" ::: "memory");
    };

    // prologue: stages 0 and 1 in flight
    load_chunk(0, 0);
    load_chunk(1, 1);

    for (int c = 0; c < nch; c++) {
        // wait for stage c (per-thread), then make all threads' copies visible
        if (c + 1 < nch) {
            asm volatile("cp.async.wait_group 1;" ::: "memory");
        } else {
            asm volatile("cp.async.wait_group 0;" ::: "memory");
        }
        __syncthreads();   // also guarantees everyone is done READING stage (c-1)

        // refill the slot freed by stage (c-1)
        if (c + 2 < nch) load_chunk(c + 2, (c + 2) % NSTAGE);

        const float* cA = smem + (c % NSTAGE) * 2 * TBUF;
        const float* cB = cA + TBUF;
        #pragma unroll
        for (int ks = 0; ks < 4; ks++) {
            const int k0 = ks * 8 + (lane & 3);
            uint32_t a[4][4], b[8][2];
            #pragma unroll
            for (int mf = 0; mf < 4; mf++) {
                const float* p = cA + (wm + mf * 16 + (lane >> 2)) * LDT + k0;
                a[mf][0] = __float_as_uint(p[0]);
                a[mf][1] = __float_as_uint(p[8 * LDT]);
                a[mf][2] = __float_as_uint(p[4]);
                a[mf][3] = __float_as_uint(p[8 * LDT + 4]);
            }
            #pragma unroll
            for (int nf = 0; nf < 8; nf++) {
                const float* p = cB + (wn + nf * 8 + (lane >> 2)) * LDT + k0;
                b[nf][0] = __float_as_uint(p[0]);
                b[nf][1] = __float_as_uint(p[4]);
            }
            #pragma unroll
            for (int mf = 0; mf < 4; mf++)
                #pragma unroll
                for (int nf = 0; nf < 8; nf++)
                    mma_tf32(acc[mf][nf], a[mf], b[nf]);
        }
    }

    const float GC = 0.7978845608028654f;
    #pragma unroll
    for (int mf = 0; mf < 4; mf++) {
        #pragma unroll
        for (int half = 0; half < 2; half++) {
            int row = bm + wm + mf * 16 + (lane >> 2) + half * 8;
            float* Crow = C + (size_t)row * N_ + bn + wn;
            const float* Rrow = res + (size_t)row * N_ + bn + wn;
            #pragma unroll
            for (int nf = 0; nf < 8; nf++) {
                int col = nf * 8 + 2 * (lane & 3);
                float2 v;
                v.x = acc[mf][nf][half * 2 + 0] + bias[bn + wn + col];
                v.y = acc[mf][nf][half * 2 + 1] + bias[bn + wn + col + 1];
                if (EPI == 1) {
                    v.x = tf32r(0.5f * v.x * (1.f + tanhf(GC * (v.x + 0.044715f * v.x * v.x * v.x))));
                    v.y = tf32r(0.5f * v.y * (1.f + tanhf(GC * (v.y + 0.044715f * v.y * v.y * v.y))));
                }
                if (EPI == 2) {
                    float2 rv = *(const float2*)(Rrow + col);
                    v.x += rv.x; v.y += rv.y;
                }
                *(float2*)(Crow + col) = v;
            }
        }
    }
}

// ============== Flash attention (causal) with tf32 mma.sync ==============
// Q-tile 128 (4 warps x 32 rows), K-tile 64, DH=64. cp.async double-buffered K/V.
#define AST 68
#define ASMEM ((2 * 128 + 4 * 64) * AST * 4)   // 139264 B

__global__ __launch_bounds__(128) void attn_kernel(const float* __restrict__ qkv,
                                                   float* __restrict__ out)
{
    extern __shared__ float smem[];
    float* Qs  = smem;                        // 128 x AST
    float* Ps  = Qs  + 128 * AST;             // 128 x AST
    float* KsB = Ps  + 128 * AST;             // 2 x 64 x AST
    float* VsB = KsB + 2 * 64 * AST;          // 2 x 64 x AST

    const int b = blockIdx.z, h = blockIdx.y, q0 = blockIdx.x << 7;
    const int tid = threadIdx.x, lane = tid & 31, wid = tid >> 5;
    const int wm = wid * 32;
    const int lp = lane >> 2, lq = lane & 3;
    const size_t base = (size_t)b * SEQ * (3 * D) + h * DH;

    for (int s = tid; s < 2048; s += 128) {
        int r = s >> 4, u = s & 15;
        float4 v = *(const float4*)(qkv + base + (size_t)(q0 + r) * (3 * D) + u * 4);
        float* dst = Qs + r * AST + u * 4;
        dst[0] = tf32r(v.x * 0.125f); dst[1] = tf32r(v.y * 0.125f);
        dst[2] = tf32r(v.z * 0.125f); dst[3] = tf32r(v.w * 0.125f);
    }

    auto load_kv = [&](int kt, int buf) {
        float* dK = KsB + buf * 64 * AST;
        float* dV = VsB + buf * 64 * AST;
        const int k0 = kt << 6;
        #pragma unroll
        for (int i = 0; i < 8; i++) {
            int s = i * 128 + tid;
            int r = s >> 4, u = s & 15;
            const float* p = qkv + base + (size_t)(k0 + r) * (3 * D) + u * 4;
            cp16(smem_u32(dK + r * AST + u * 4), p + D);
            cp16(smem_u32(dV + r * AST + u * 4), p + 2 * D);
        }
        asm volatile("cp.async.commit_group;" ::: "memory");
    };

    float m_i[2][2], l_i[2][2], ao[2][8][4];
    #pragma unroll
    for (int mf = 0; mf < 2; mf++)
        #pragma unroll
        for (int hf = 0; hf < 2; hf++) { m_i[mf][hf] = -1e30f; l_i[mf][hf] = 0.f; }
    #pragma unroll
    for (int mf = 0; mf < 2; mf++)
        #pragma unroll
        for (int nf = 0; nf < 8; nf++)
            #pragma unroll
            for (int q = 0; q < 4; q++) ao[mf][nf][q] = 0.f;

    const int ntiles = (q0 >> 6) + 2;
    load_kv(0, 0);
    __syncthreads();

    for (int kt = 0; kt < ntiles; kt++) {
        const int buf = kt & 1;
        const int k0 = kt << 6;
        if (kt + 1 < ntiles) {
            load_kv(kt + 1, buf ^ 1);
            asm volatile("cp.async.wait_group 1;" ::: "memory");
        } else {
            asm volatile("cp.async.wait_group 0;" ::: "memory");
        }
        __syncthreads();
        const float* Ks = KsB + buf * 64 * AST;
        const float* Vs = VsB + buf * 64 * AST;

        float sc[2][8][4];
        #pragma unroll
        for (int mf = 0; mf < 2; mf++)
            #pragma unroll
            for (int nf = 0; nf < 8; nf++)
                #pragma unroll
                for (int q = 0; q < 4; q++) sc[mf][nf][q] = 0.f;
        #pragma unroll
        for (int kc = 0; kc < 8; kc++) {
            const int kk = kc * 8 + lq;
            uint32_t a[2][4], bfr[8][2];
            #pragma unroll
            for (int mf = 0; mf < 2; mf++) {
                const float* p = Qs + (wm + mf * 16 + lp) * AST + kk;
                a[mf][0] = __float_as_uint(p[0]);
                a[mf][1] = __float_as_uint(p[8 * AST]);
                a[mf][2] = __float_as_uint(p[4]);
                a[mf][3] = __float_as_uint(p[8 * AST + 4]);
            }
            #pragma unroll
            for (int nf = 0; nf < 8; nf++) {
                const float* p = Ks + (nf * 8 + lp) * AST + kk;
                bfr[nf][0] = __float_as_uint(p[0]);
                bfr[nf][1] = __float_as_uint(p[4]);
            }
            #pragma unroll
            for (int mf = 0; mf < 2; mf++)
                #pragma unroll
                for (int nf = 0; nf < 8; nf++)
                    mma_tf32(sc[mf][nf], a[mf], bfr[nf]);
        }

        if (kt >= ntiles - 2) {
            #pragma unroll
            for (int mf = 0; mf < 2; mf++)
                #pragma unroll
                for (int hf = 0; hf < 2; hf++) {
                    int row = q0 + wm + mf * 16 + lp + hf * 8;
                    #pragma unroll
                    for (int nf = 0; nf < 8; nf++) {
                        int col = k0 + nf * 8 + 2 * lq;
                        if (col > row)     sc[mf][nf][hf * 2 + 0] = -10000.0f;
                        if (col + 1 > row) sc[mf][nf][hf * 2 + 1] = -10000.0f;
                    }
                }
        }

        #pragma unroll
        for (int mf = 0; mf < 2; mf++)
            #pragma unroll
            for (int hf = 0; hf < 2; hf++) {
                float mx = sc[mf][0][hf * 2];
                #pragma unroll
                for (int nf = 0; nf < 8; nf++) {
                    mx = fmaxf(mx, sc[mf][nf][hf * 2 + 0]);
                    mx = fmaxf(mx, sc[mf][nf][hf * 2 + 1]);
                }
                mx = fmaxf(mx, __shfl_xor_sync(0xffffffffu, mx, 1, 4));
                mx = fmaxf(mx, __shfl_xor_sync(0xffffffffu, mx, 2, 4));
                float mnew = fmaxf(m_i[mf][hf], mx);
                float corr = __expf(m_i[mf][hf] - mnew);
                float sum = 0.f;
                #pragma unroll
                for (int nf = 0; nf < 8; nf++) {
                    float p0 = __expf(sc[mf][nf][hf * 2 + 0] - mnew);
                    float p1 = __expf(sc[mf][nf][hf * 2 + 1] - mnew);
                    sc[mf][nf][hf * 2 + 0] = p0;
                    sc[mf][nf][hf * 2 + 1] = p1;
                    sum += p0 + p1;
                }
                sum += __shfl_xor_sync(0xffffffffu, sum, 1, 4);
                sum += __shfl_xor_sync(0xffffffffu, sum, 2, 4);
                l_i[mf][hf] = l_i[mf][hf] * corr + sum;
                m_i[mf][hf] = mnew;
                #pragma unroll
                for (int nf = 0; nf < 8; nf++) {
                    ao[mf][nf][hf * 2 + 0] *= corr;
                    ao[mf][nf][hf * 2 + 1] *= corr;
                }
            }

        #pragma unroll
        for (int mf = 0; mf < 2; mf++) {
            int row0 = wm + mf * 16 + lp;
            #pragma unroll
            for (int nf = 0; nf < 8; nf++) {
                int col = nf * 8 + 2 * lq;
                *(float2*)(Ps + row0 * AST + col)       = make_float2(sc[mf][nf][0], sc[mf][nf][1]);
                *(float2*)(Ps + (row0 + 8) * AST + col) = make_float2(sc[mf][nf][2], sc[mf][nf][3]);
            }
        }
        __syncwarp();

        #pragma unroll
        for (int kc = 0; kc < 8; kc++) {
            const int kk = kc * 8 + lq;
            uint32_t a[2][4], bfr[8][2];
            #pragma unroll
            for (int mf = 0; mf < 2; mf++) {
                const float* p = Ps + (wm + mf * 16 + lp) * AST + kk;
                a[mf][0] = __float_as_uint(p[0]);
                a[mf][1] = __float_as_uint(p[8 * AST]);
                a[mf][2] = __float_as_uint(p[4]);
                a[mf][3] = __float_as_uint(p[8 * AST + 4]);
            }
            #pragma unroll
            for (int nf = 0; nf < 8; nf++) {
                const float* p0 = Vs + kk * AST + nf * 8 + lp;
                const float* p1 = Vs + (kk + 4) * AST + nf * 8 + lp;
                bfr[nf][0] = __float_as_uint(p0[0]);
                bfr[nf][1] = __float_as_uint(p1[0]);
            }
            #pragma unroll
            for (int mf = 0; mf < 2; mf++)
                #pragma unroll
                for (int nf = 0; nf < 8; nf++)
                    mma_tf32(ao[mf][nf], a[mf], bfr[nf]);
        }
        __syncthreads();
    }

    #pragma unroll
    for (int mf = 0; mf < 2; mf++)
        #pragma unroll
        for (int hf = 0; hf < 2; hf++) {
            float inv = 1.f / l_i[mf][hf];
            int row = q0 + wm + mf * 16 + lp + hf * 8;
            float* orow = out + (size_t)(b * SEQ + row) * D + h * DH;
            #pragma unroll
            for (int nf = 0; nf < 8; nf++) {
                int col = nf * 8 + 2 * lq;
                *(float2*)(orow + col) = make_float2(tf32r(ao[mf][nf][hf * 2 + 0] * inv),
                                                     tf32r(ao[mf][nf][hf * 2 + 1] * inv));
            }
        }
}

// ---------------- launch ----------------
extern "C" void kernel_launch(void* const* d_in, const int* in_sizes, int n_in,
                              void* d_out, int out_size)
{
    const float* hs    = (const float*)d_in[0];
    const float* ln1g  = (const float*)d_in[1];
    const float* ln1b  = (const float*)d_in[2];
    const float* wattn = (const float*)d_in[3];
    const float* battn = (const float*)d_in[4];
    const float* wproj = (const float*)d_in[5];
    const float* bproj = (const float*)d_in[6];
    const float* ln2g  = (const float*)d_in[7];
    const float* ln2b  = (const float*)d_in[8];
    const float* wfc   = (const float*)d_in[9];
    const float* bfc   = (const float*)d_in[10];
    const float* wmlp  = (const float*)d_in[11];
    const float* bmlp  = (const float*)d_in[12];
    float* out = (float*)d_out;

    int tokens = in_sizes[0] / D;   // 8192
    int B = tokens / SEQ;

    float *xln, *qkvb, *attnb, *resb, *mlnb, *fcb;
    float *wattn_t, *wproj_t, *wfc_t, *wmlp_t;
    cudaGetSymbolAddress((void**)&xln,   g_xln);
    cudaGetSymbolAddress((void**)&qkvb,  g_qkv);
    cudaGetSymbolAddress((void**)&attnb, g_attn);
    cudaGetSymbolAddress((void**)&resb,  g_res);
    cudaGetSymbolAddress((void**)&mlnb,  g_mln);
    cudaGetSymbolAddress((void**)&fcb,   g_fc);
    cudaGetSymbolAddress((void**)&wattn_t, g_wattn_t);
    cudaGetSymbolAddress((void**)&wproj_t, g_wproj_t);
    cudaGetSymbolAddress((void**)&wfc_t,   g_wfc_t);
    cudaGetSymbolAddress((void**)&wmlp_t,  g_wmlp_t);

    cudaFuncSetAttribute(tc_gemm<0>, cudaFuncAttributeMaxDynamicSharedMemorySize, GSMEM);
    cudaFuncSetAttribute(tc_gemm<1>, cudaFuncAttributeMaxDynamicSharedMemorySize, GSMEM);
    cudaFuncSetAttribute(tc_gemm<2>, cudaFuncAttributeMaxDynamicSharedMemorySize, GSMEM);
    cudaFuncSetAttribute(attn_kernel, cudaFuncAttributeMaxDynamicSharedMemorySize, ASMEM);

    // weight transposes (Bt[N][K] K-major, tf32-rounded)
    transpose_kernel<<<dim3(3 * D / 32, D / 32), 256>>>(wattn, wattn_t, D, 3 * D);
    transpose_kernel<<<dim3(D / 32, D / 32), 256>>>(wproj, wproj_t, D, D);
    transpose_kernel<<<dim3(FF / 32, D / 32), 256>>>(wfc, wfc_t, D, FF);
    transpose_kernel<<<dim3(D / 32, FF / 32), 256>>>(wmlp, wmlp_t, FF, D);

    // LN1
    ln_kernel<<<tokens, 256>>>(hs, ln1g, ln1b, xln);

    // QKV = xln @ w_attn + b_attn
    tc_gemm<0><<<dim3(3 * D / BN, tokens / BM), 128, GSMEM>>>(
        xln, wattn_t, battn, nullptr, qkvb, tokens, 3 * D, D);

    // attention (tf32 mma flash attention)
    attn_kernel<<<dim3(SEQ / 128, H, B), 128, ASMEM>>>(qkvb, attnb);

    // resid = hs + attnb @ w_attn_proj + b_attn_proj
    tc_gemm<2><<<dim3(D / BN, tokens / BM), 128, GSMEM>>>(
        attnb, wproj_t, bproj, hs, resb, tokens, D, D);

    // LN2
    ln_kernel<<<tokens, 256>>>(resb, ln2g, ln2b, mlnb);

    // fc = gelu_new(mlnb @ w_fc + b_fc)
    tc_gemm<1><<<dim3(FF / BN, tokens / BM), 128, GSMEM>>>(
        mlnb, wfc_t, bfc, nullptr, fcb, tokens, FF, D);

    // out = resb + fcb @ w_mlp_proj + b_mlp_proj
    tc_gemm<2><<<dim3(D / BN, tokens / BM), 128, GSMEM>>>(
        fcb, wmlp_t, bmlp, resb, out, tokens, D, FF);
}

// round 8
// speedup vs baseline: 1.4716x; 1.4716x over previous
#include <cuda_runtime.h>
#include <cstdint>

// Problem constants
#define D   1024
#define H   16
#define DH  64
#define FF  4096
#define SEQ 2048
#define MAXTOK 8192   // B=4 * S=2048

// ---------------- scratch (static device globals; no allocation) ----------------
__device__ float g_xln [MAXTOK * D];
__device__ float g_qkv [MAXTOK * 3 * D];
__device__ float g_attn[MAXTOK * D];
__device__ float g_res [MAXTOK * D];
__device__ float g_mln [MAXTOK * D];
__device__ float g_fc  [(size_t)MAXTOK * FF];
__device__ float g_wattn_t[3 * D * D];
__device__ float g_wproj_t[D * D];
__device__ float g_wfc_t  [FF * D];
__device__ float g_wmlp_t [D * FF];

// ---------------- helpers ----------------
__device__ __forceinline__ uint32_t smem_u32(const void* p){
    uint32_t a;
    asm("{ .reg .u64 t; cvta.to.shared.u64 t, %1; cvt.u32.u64 %0, t; }" : "=r"(a) : "l"(p));
    return a;
}
__device__ __forceinline__ float tf32r(float x){
    uint32_t u; asm("cvt.rna.tf32.f32 %0, %1;" : "=r"(u) : "f"(x));
    return __uint_as_float(u);
}
__device__ __forceinline__ void mma_tf32(float* c, const uint32_t* a, const uint32_t* b){
    asm volatile(
        "mma.sync.aligned.m16n8k8.row.col.f32.tf32.tf32.f32 "
        "{%0,%1,%2,%3}, {%4,%5,%6,%7}, {%8,%9}, {%0,%1,%2,%3};\n"
        : "+f"(c[0]), "+f"(c[1]), "+f"(c[2]), "+f"(c[3])
        : "r"(a[0]), "r"(a[1]), "r"(a[2]), "r"(a[3]), "r"(b[0]), "r"(b[1]));
}
__device__ __forceinline__ void cp16(uint32_t smem_addr, const void* gptr){
    asm volatile("cp.async.cg.shared.global [%0], [%1], 16;" :: "r"(smem_addr), "l"(gptr));
}

// ---------------- transpose: in[R][C] -> out[C][R], rounded to tf32 ----------------
__global__ __launch_bounds__(256) void transpose_kernel(const float* __restrict__ in,
                                                        float* __restrict__ out, int R, int C)
{
    __shared__ float t[32][33];
    int bx = blockIdx.x * 32, by = blockIdx.y * 32;
    int x = threadIdx.x & 31, y0 = threadIdx.x >> 5;
    #pragma unroll
    for (int yy = y0; yy < 32; yy += 8)
        t[yy][x] = in[(size_t)(by + yy) * C + bx + x];
    __syncthreads();
    #pragma unroll
    for (int yy = y0; yy < 32; yy += 8)
        out[(size_t)(bx + yy) * R + by + x] = tf32r(t[x][yy]);
}

// ---------------- LayerNorm (output rounded to tf32: feeds GEMM A) ----------------
__global__ __launch_bounds__(256) void ln_kernel(const float* __restrict__ in,
                                                 const float* __restrict__ gw,
                                                 const float* __restrict__ bw,
                                                 float* __restrict__ out)
{
    __shared__ float red0[8], red1[8];
    int row = blockIdx.x, tid = threadIdx.x;
    const float4* x4 = (const float4*)(in + (size_t)row * D);
    float4 v = x4[tid];
    float s  = v.x + v.y + v.z + v.w;
    float ss = v.x*v.x + v.y*v.y + v.z*v.z + v.w*v.w;
    #pragma unroll
    for (int o = 16; o; o >>= 1) {
        s  += __shfl_xor_sync(0xffffffffu, s,  o);
        ss += __shfl_xor_sync(0xffffffffu, ss, o);
    }
    if ((tid & 31) == 0) { red0[tid >> 5] = s; red1[tid >> 5] = ss; }
    __syncthreads();
    s = 0.f; ss = 0.f;
    #pragma unroll
    for (int i = 0; i < 8; i++) { s += red0[i]; ss += red1[i]; }
    float mean = s * (1.f / D);
    float var  = ss * (1.f / D) - mean * mean;
    float rstd = rsqrtf(var + 1e-5f);
    float4 gv = ((const float4*)gw)[tid];
    float4 bv = ((const float4*)bw)[tid];
    float4 o4;
    o4.x = tf32r((v.x - mean) * rstd * gv.x + bv.x);
    o4.y = tf32r((v.y - mean) * rstd * gv.y + bv.y);
    o4.z = tf32r((v.z - mean) * rstd * gv.z + bv.z);
    o4.w = tf32r((v.w - mean) * rstd * gv.w + bv.w);
    ((float4*)(out + (size_t)row * D))[tid] = o4;
}

// ============== mma.sync tf32 GEMM (ROUND-5 PROVEN CONFIG: 2-stage, 3 CTAs/SM) ==============
#define BM 128
#define BN 128
#define BK 32
#define LDT 36
#define TBUF (128 * LDT)
#define GSMEM (4 * TBUF * 4)     // 73728 B -> 3 CTAs/SM

template<int EPI>
__global__ __launch_bounds__(128) void tc_gemm(const float* __restrict__ A,
                                               const float* __restrict__ Bt,
                                               const float* __restrict__ bias,
                                               const float* __restrict__ res,
                                               float* __restrict__ C,
                                               int M, int N_, int K)
{
    extern __shared__ float smem[];
    float* AsBase = smem;
    float* BsBase = smem + 2 * TBUF;
    const int tid = threadIdx.x, lane = tid & 31, wid = tid >> 5;
    const int wm = (wid >> 1) * 64, wn = (wid & 1) * 64;
    const int bm = blockIdx.y * BM, bn = blockIdx.x * BN;
    const int nch = K / BK;

    const float* Ag = A  + (size_t)bm * K;
    const float* Bg = Bt + (size_t)bn * K;

    float acc[4][8][4];
    #pragma unroll
    for (int mf = 0; mf < 4; mf++)
        #pragma unroll
        for (int nf = 0; nf < 8; nf++)
            #pragma unroll
            for (int q = 0; q < 4; q++) acc[mf][nf][q] = 0.f;

    auto load_chunk = [&](int c, int buf) {
        float* dA = AsBase + buf * TBUF;
        float* dB = BsBase + buf * TBUF;
        const float* a0 = Ag + c * BK;
        const float* b0 = Bg + c * BK;
        #pragma unroll
        for (int i = 0; i < 8; i++) {
            int slot = i * 128 + tid;
            int r = slot >> 3, u = slot & 7;
            cp16(smem_u32(dA + r * LDT + u * 4), a0 + (size_t)r * K + u * 4);
            cp16(smem_u32(dB + r * LDT + u * 4), b0 + (size_t)r * K + u * 4);
        }
        asm volatile("cp.async.commit_group;" ::: "memory");
    };

    load_chunk(0, 0);

    for (int c = 0; c < nch; c++) {
        if (c + 1 < nch) {
            load_chunk(c + 1, (c + 1) & 1);
            asm volatile("cp.async.wait_group 1;" ::: "memory");
        } else {
            asm volatile("cp.async.wait_group 0;" ::: "memory");
        }
        __syncthreads();
        const float* cA = AsBase + (c & 1) * TBUF;
        const float* cB = BsBase + (c & 1) * TBUF;
        #pragma unroll
        for (int ks = 0; ks < 4; ks++) {
            const int k0 = ks * 8 + (lane & 3);
            uint32_t a[4][4], b[8][2];
            #pragma unroll
            for (int mf = 0; mf < 4; mf++) {
                const float* p = cA + (wm + mf * 16 + (lane >> 2)) * LDT + k0;
                a[mf][0] = __float_as_uint(p[0]);
                a[mf][1] = __float_as_uint(p[8 * LDT]);
                a[mf][2] = __float_as_uint(p[4]);
                a[mf][3] = __float_as_uint(p[8 * LDT + 4]);
            }
            #pragma unroll
            for (int nf = 0; nf < 8; nf++) {
                const float* p = cB + (wn + nf * 8 + (lane >> 2)) * LDT + k0;
                b[nf][0] = __float_as_uint(p[0]);
                b[nf][1] = __float_as_uint(p[4]);
            }
            #pragma unroll
            for (int mf = 0; mf < 4; mf++)
                #pragma unroll
                for (int nf = 0; nf < 8; nf++)
                    mma_tf32(acc[mf][nf], a[mf], b[nf]);
        }
        __syncthreads();
    }

    const float GC = 0.7978845608028654f;
    #pragma unroll
    for (int mf = 0; mf < 4; mf++) {
        #pragma unroll
        for (int half = 0; half < 2; half++) {
            int row = bm + wm + mf * 16 + (lane >> 2) + half * 8;
            float* Crow = C + (size_t)row * N_ + bn + wn;
            const float* Rrow = res + (size_t)row * N_ + bn + wn;
            #pragma unroll
            for (int nf = 0; nf < 8; nf++) {
                int col = nf * 8 + 2 * (lane & 3);
                float2 v;
                v.x = acc[mf][nf][half * 2 + 0] + bias[bn + wn + col];
                v.y = acc[mf][nf][half * 2 + 1] + bias[bn + wn + col + 1];
                if (EPI == 1) {
                    v.x = tf32r(0.5f * v.x * (1.f + tanhf(GC * (v.x + 0.044715f * v.x * v.x * v.x))));
                    v.y = tf32r(0.5f * v.y * (1.f + tanhf(GC * (v.y + 0.044715f * v.y * v.y * v.y))));
                }
                if (EPI == 2) {
                    float2 rv = *(const float2*)(Rrow + col);
                    v.x += rv.x; v.y += rv.y;
                }
                *(float2*)(Crow + col) = v;
            }
        }
    }
}

// ============== Flash attention (causal) with tf32 mma.sync, 256 threads ==============
// Q-tile 128 (8 warps x 16 rows), K-tile 64, DH=64. cp.async double-buffered K/V.
#define AST 68
#define ASMEM ((2 * 128 + 4 * 64) * AST * 4)   // 139264 B

__global__ __launch_bounds__(256) void attn_kernel(const float* __restrict__ qkv,
                                                   float* __restrict__ out)
{
    extern __shared__ float smem[];
    float* Qs  = smem;                        // 128 x AST
    float* Ps  = Qs  + 128 * AST;             // 128 x AST
    float* KsB = Ps  + 128 * AST;             // 2 x 64 x AST
    float* VsB = KsB + 2 * 64 * AST;          // 2 x 64 x AST

    const int b = blockIdx.z, h = blockIdx.y, q0 = blockIdx.x << 7;
    const int tid = threadIdx.x, lane = tid & 31, wid = tid >> 5;
    const int wm = wid * 16;                  // warp's q-row offset (8 warps x 16 rows)
    const int lp = lane >> 2, lq = lane & 3;
    const size_t base = (size_t)b * SEQ * (3 * D) + h * DH;

    // load Q tile, scaled by 1/sqrt(DH)=0.125, tf32-rounded
    for (int s = tid; s < 2048; s += 256) {
        int r = s >> 4, u = s & 15;
        float4 v = *(const float4*)(qkv + base + (size_t)(q0 + r) * (3 * D) + u * 4);
        float* dst = Qs + r * AST + u * 4;
        dst[0] = tf32r(v.x * 0.125f); dst[1] = tf32r(v.y * 0.125f);
        dst[2] = tf32r(v.z * 0.125f); dst[3] = tf32r(v.w * 0.125f);
    }

    auto load_kv = [&](int kt, int buf) {
        float* dK = KsB + buf * 64 * AST;
        float* dV = VsB + buf * 64 * AST;
        const int k0 = kt << 6;
        #pragma unroll
        for (int i = 0; i < 4; i++) {
            int s = i * 256 + tid;
            int r = s >> 4, u = s & 15;
            const float* p = qkv + base + (size_t)(k0 + r) * (3 * D) + u * 4;
            cp16(smem_u32(dK + r * AST + u * 4), p + D);
            cp16(smem_u32(dV + r * AST + u * 4), p + 2 * D);
        }
        asm volatile("cp.async.commit_group;" ::: "memory");
    };

    float m_i[2], l_i[2], ao[8][4];
    #pragma unroll
    for (int hf = 0; hf < 2; hf++) { m_i[hf] = -1e30f; l_i[hf] = 0.f; }
    #pragma unroll
    for (int nf = 0; nf < 8; nf++)
        #pragma unroll
        for (int q = 0; q < 4; q++) ao[nf][q] = 0.f;

    const int ntiles = (q0 >> 6) + 2;
    load_kv(0, 0);
    __syncthreads();

    for (int kt = 0; kt < ntiles; kt++) {
        const int buf = kt & 1;
        const int k0 = kt << 6;
        if (kt + 1 < ntiles) {
            load_kv(kt + 1, buf ^ 1);
            asm volatile("cp.async.wait_group 1;" ::: "memory");
        } else {
            asm volatile("cp.async.wait_group 0;" ::: "memory");
        }
        __syncthreads();
        const float* Ks = KsB + buf * 64 * AST;
        const float* Vs = VsB + buf * 64 * AST;

        // ---- S = Q K^T : warptile 16(M) x 64(N) ----
        float sc[8][4];
        #pragma unroll
        for (int nf = 0; nf < 8; nf++)
            #pragma unroll
            for (int q = 0; q < 4; q++) sc[nf][q] = 0.f;
        #pragma unroll
        for (int kc = 0; kc < 8; kc++) {
            const int kk = kc * 8 + lq;
            uint32_t a[4], bfr[8][2];
            {
                const float* p = Qs + (wm + lp) * AST + kk;
                a[0] = __float_as_uint(p[0]);
                a[1] = __float_as_uint(p[8 * AST]);
                a[2] = __float_as_uint(p[4]);
                a[3] = __float_as_uint(p[8 * AST + 4]);
            }
            #pragma unroll
            for (int nf = 0; nf < 8; nf++) {
                const float* p = Ks + (nf * 8 + lp) * AST + kk;
                bfr[nf][0] = __float_as_uint(p[0]);
                bfr[nf][1] = __float_as_uint(p[4]);
            }
            #pragma unroll
            for (int nf = 0; nf < 8; nf++)
                mma_tf32(sc[nf], a, bfr[nf]);
        }

        // ---- causal mask on last two tiles ----
        if (kt >= ntiles - 2) {
            #pragma unroll
            for (int hf = 0; hf < 2; hf++) {
                int row = q0 + wm + lp + hf * 8;
                #pragma unroll
                for (int nf = 0; nf < 8; nf++) {
                    int col = k0 + nf * 8 + 2 * lq;
                    if (col > row)     sc[nf][hf * 2 + 0] = -10000.0f;
                    if (col + 1 > row) sc[nf][hf * 2 + 1] = -10000.0f;
                }
            }
        }

        // ---- online softmax per row-slot ----
        #pragma unroll
        for (int hf = 0; hf < 2; hf++) {
            float mx = sc[0][hf * 2];
            #pragma unroll
            for (int nf = 0; nf < 8; nf++) {
                mx = fmaxf(mx, sc[nf][hf * 2 + 0]);
                mx = fmaxf(mx, sc[nf][hf * 2 + 1]);
            }
            mx = fmaxf(mx, __shfl_xor_sync(0xffffffffu, mx, 1, 4));
            mx = fmaxf(mx, __shfl_xor_sync(0xffffffffu, mx, 2, 4));
            float mnew = fmaxf(m_i[hf], mx);
            float corr = __expf(m_i[hf] - mnew);
            float sum = 0.f;
            #pragma unroll
            for (int nf = 0; nf < 8; nf++) {
                float p0 = __expf(sc[nf][hf * 2 + 0] - mnew);
                float p1 = __expf(sc[nf][hf * 2 + 1] - mnew);
                sc[nf][hf * 2 + 0] = p0;
                sc[nf][hf * 2 + 1] = p1;
                sum += p0 + p1;
            }
            sum += __shfl_xor_sync(0xffffffffu, sum, 1, 4);
            sum += __shfl_xor_sync(0xffffffffu, sum, 2, 4);
            l_i[hf] = l_i[hf] * corr + sum;
            m_i[hf] = mnew;
            #pragma unroll
            for (int nf = 0; nf < 8; nf++) {
                ao[nf][hf * 2 + 0] *= corr;
                ao[nf][hf * 2 + 1] *= corr;
            }
        }

        // ---- stage P (warp-private 16 rows) ----
        {
            int row0 = wm + lp;
            #pragma unroll
            for (int nf = 0; nf < 8; nf++) {
                int col = nf * 8 + 2 * lq;
                *(float2*)(Ps + row0 * AST + col)       = make_float2(sc[nf][0], sc[nf][1]);
                *(float2*)(Ps + (row0 + 8) * AST + col) = make_float2(sc[nf][2], sc[nf][3]);
            }
        }
        __syncwarp();

        // ---- O += P V ----
        #pragma unroll
        for (int kc = 0; kc < 8; kc++) {
            const int kk = kc * 8 + lq;
            uint32_t a[4], bfr[8][2];
            {
                const float* p = Ps + (wm + lp) * AST + kk;
                a[0] = __float_as_uint(p[0]);
                a[1] = __float_as_uint(p[8 * AST]);
                a[2] = __float_as_uint(p[4]);
                a[3] = __float_as_uint(p[8 * AST + 4]);
            }
            #pragma unroll
            for (int nf = 0; nf < 8; nf++) {
                const float* p0 = Vs + kk * AST + nf * 8 + lp;
                const float* p1 = Vs + (kk + 4) * AST + nf * 8 + lp;
                bfr[nf][0] = __float_as_uint(p0[0]);
                bfr[nf][1] = __float_as_uint(p1[0]);
            }
            #pragma unroll
            for (int nf = 0; nf < 8; nf++)
                mma_tf32(ao[nf], a, bfr[nf]);
        }
        __syncthreads();
    }

    // ---- write O (tf32-rounded: feeds attn-proj GEMM as A) ----
    #pragma unroll
    for (int hf = 0; hf < 2; hf++) {
        float inv = 1.f / l_i[hf];
        int row = q0 + wm + lp + hf * 8;
        float* orow = out + (size_t)(b * SEQ + row) * D + h * DH;
        #pragma unroll
        for (int nf = 0; nf < 8; nf++) {
            int col = nf * 8 + 2 * lq;
            *(float2*)(orow + col) = make_float2(tf32r(ao[hf * 2 + 0 >= 2 ? nf : nf][hf * 2 + 0] * inv),
                                                 tf32r(ao[nf][hf * 2 + 1] * inv));
        }
    }
}

// ---------------- launch ----------------
extern "C" void kernel_launch(void* const* d_in, const int* in_sizes, int n_in,
                              void* d_out, int out_size)
{
    const float* hs    = (const float*)d_in[0];
    const float* ln1g  = (const float*)d_in[1];
    const float* ln1b  = (const float*)d_in[2];
    const float* wattn = (const float*)d_in[3];
    const float* battn = (const float*)d_in[4];
    const float* wproj = (const float*)d_in[5];
    const float* bproj = (const float*)d_in[6];
    const float* ln2g  = (const float*)d_in[7];
    const float* ln2b  = (const float*)d_in[8];
    const float* wfc   = (const float*)d_in[9];
    const float* bfc   = (const float*)d_in[10];
    const float* wmlp  = (const float*)d_in[11];
    const float* bmlp  = (const float*)d_in[12];
    float* out = (float*)d_out;

    int tokens = in_sizes[0] / D;   // 8192
    int B = tokens / SEQ;

    float *xln, *qkvb, *attnb, *resb, *mlnb, *fcb;
    float *wattn_t, *wproj_t, *wfc_t, *wmlp_t;
    cudaGetSymbolAddress((void**)&xln,   g_xln);
    cudaGetSymbolAddress((void**)&qkvb,  g_qkv);
    cudaGetSymbolAddress((void**)&attnb, g_attn);
    cudaGetSymbolAddress((void**)&resb,  g_res);
    cudaGetSymbolAddress((void**)&mlnb,  g_mln);
    cudaGetSymbolAddress((void**)&fcb,   g_fc);
    cudaGetSymbolAddress((void**)&wattn_t, g_wattn_t);
    cudaGetSymbolAddress((void**)&wproj_t, g_wproj_t);
    cudaGetSymbolAddress((void**)&wfc_t,   g_wfc_t);
    cudaGetSymbolAddress((void**)&wmlp_t,  g_wmlp_t);

    cudaFuncSetAttribute(tc_gemm<0>, cudaFuncAttributeMaxDynamicSharedMemorySize, GSMEM);
    cudaFuncSetAttribute(tc_gemm<1>, cudaFuncAttributeMaxDynamicSharedMemorySize, GSMEM);
    cudaFuncSetAttribute(tc_gemm<2>, cudaFuncAttributeMaxDynamicSharedMemorySize, GSMEM);
    cudaFuncSetAttribute(attn_kernel, cudaFuncAttributeMaxDynamicSharedMemorySize, ASMEM);

    // weight transposes (Bt[N][K] K-major, tf32-rounded)
    transpose_kernel<<<dim3(3 * D / 32, D / 32), 256>>>(wattn, wattn_t, D, 3 * D);
    transpose_kernel<<<dim3(D / 32, D / 32), 256>>>(wproj, wproj_t, D, D);
    transpose_kernel<<<dim3(FF / 32, D / 32), 256>>>(wfc, wfc_t, D, FF);
    transpose_kernel<<<dim3(D / 32, FF / 32), 256>>>(wmlp, wmlp_t, FF, D);

    // LN1
    ln_kernel<<<tokens, 256>>>(hs, ln1g, ln1b, xln);

    // QKV = xln @ w_attn + b_attn
    tc_gemm<0><<<dim3(3 * D / BN, tokens / BM), 128, GSMEM>>>(
        xln, wattn_t, battn, nullptr, qkvb, tokens, 3 * D, D);

    // attention (tf32 mma flash attention, 256 threads)
    attn_kernel<<<dim3(SEQ / 128, H, B), 256, ASMEM>>>(qkvb, attnb);

    // resid = hs + attnb @ w_attn_proj + b_attn_proj
    tc_gemm<2><<<dim3(D / BN, tokens / BM), 128, GSMEM>>>(
        attnb, wproj_t, bproj, hs, resb, tokens, D, D);

    // LN2
    ln_kernel<<<tokens, 256>>>(resb, ln2g, ln2b, mlnb);

    // fc = gelu_new(mlnb @ w_fc + b_fc)
    tc_gemm<1><<<dim3(FF / BN, tokens / BM), 128, GSMEM>>>(
        mlnb, wfc_t, bfc, nullptr, fcb, tokens, FF, D);

    // out = resb + fcb @ w_mlp_proj + b_mlp_proj
    tc_gemm<2><<<dim3(D / BN, tokens / BM), 128, GSMEM>>>(
        fcb, wmlp_t, bmlp, resb, out, tokens, D, FF);
}

// round 9
// speedup vs baseline: 1.6418x; 1.1157x over previous
#include <cuda_runtime.h>
#include <cstdint>

// Problem constants
#define D   1024
#define H   16
#define DH  64
#define FF  4096
#define SEQ 2048
#define MAXTOK 8192   // B=4 * S=2048

// ---------------- scratch (static device globals; no allocation) ----------------
__device__ float g_xln [MAXTOK * D];
__device__ float g_qkv [MAXTOK * 3 * D];
__device__ float g_attn[MAXTOK * D];
__device__ float g_res [MAXTOK * D];
__device__ float g_mln [MAXTOK * D];
__device__ float g_fc  [(size_t)MAXTOK * FF];
__device__ float g_wattn_t[3 * D * D];
__device__ float g_wproj_t[D * D];
__device__ float g_wfc_t  [FF * D];
__device__ float g_wmlp_t [D * FF];

// ---------------- helpers ----------------
__device__ __forceinline__ uint32_t smem_u32(const void* p){
    uint32_t a;
    asm("{ .reg .u64 t; cvta.to.shared.u64 t, %1; cvt.u32.u64 %0, t; }" : "=r"(a) : "l"(p));
    return a;
}
__device__ __forceinline__ float tf32r(float x){
    uint32_t u; asm("cvt.rna.tf32.f32 %0, %1;" : "=r"(u) : "f"(x));
    return __uint_as_float(u);
}
__device__ __forceinline__ void mma_tf32(float* c, const uint32_t* a, const uint32_t* b){
    asm volatile(
        "mma.sync.aligned.m16n8k8.row.col.f32.tf32.tf32.f32 "
        "{%0,%1,%2,%3}, {%4,%5,%6,%7}, {%8,%9}, {%0,%1,%2,%3};\n"
        : "+f"(c[0]), "+f"(c[1]), "+f"(c[2]), "+f"(c[3])
        : "r"(a[0]), "r"(a[1]), "r"(a[2]), "r"(a[3]), "r"(b[0]), "r"(b[1]));
}
__device__ __forceinline__ void ldsm4(uint32_t& r0, uint32_t& r1, uint32_t& r2, uint32_t& r3,
                                      const void* p){
    asm volatile("ldmatrix.sync.aligned.m8n8.x4.shared.b16 {%0,%1,%2,%3}, [%4];"
        : "=r"(r0), "=r"(r1), "=r"(r2), "=r"(r3) : "r"(smem_u32(p)));
}
__device__ __forceinline__ void cp16(uint32_t smem_addr, const void* gptr){
    asm volatile("cp.async.cg.shared.global [%0], [%1], 16;" :: "r"(smem_addr), "l"(gptr));
}

// ---------------- transpose: in[R][C] -> out[C][R], rounded to tf32 ----------------
__global__ __launch_bounds__(256) void transpose_kernel(const float* __restrict__ in,
                                                        float* __restrict__ out, int R, int C)
{
    __shared__ float t[32][33];
    int bx = blockIdx.x * 32, by = blockIdx.y * 32;
    int x = threadIdx.x & 31, y0 = threadIdx.x >> 5;
    #pragma unroll
    for (int yy = y0; yy < 32; yy += 8)
        t[yy][x] = in[(size_t)(by + yy) * C + bx + x];
    __syncthreads();
    #pragma unroll
    for (int yy = y0; yy < 32; yy += 8)
        out[(size_t)(bx + yy) * R + by + x] = tf32r(t[x][yy]);
}

// ---------------- LayerNorm (output rounded to tf32: feeds GEMM A) ----------------
__global__ __launch_bounds__(256) void ln_kernel(const float* __restrict__ in,
                                                 const float* __restrict__ gw,
                                                 const float* __restrict__ bw,
                                                 float* __restrict__ out)
{
    __shared__ float red0[8], red1[8];
    int row = blockIdx.x, tid = threadIdx.x;
    const float4* x4 = (const float4*)(in + (size_t)row * D);
    float4 v = x4[tid];
    float s  = v.x + v.y + v.z + v.w;
    float ss = v.x*v.x + v.y*v.y + v.z*v.z + v.w*v.w;
    #pragma unroll
    for (int o = 16; o; o >>= 1) {
        s  += __shfl_xor_sync(0xffffffffu, s,  o);
        ss += __shfl_xor_sync(0xffffffffu, ss, o);
    }
    if ((tid & 31) == 0) { red0[tid >> 5] = s; red1[tid >> 5] = ss; }
    __syncthreads();
    s = 0.f; ss = 0.f;
    #pragma unroll
    for (int i = 0; i < 8; i++) { s += red0[i]; ss += red1[i]; }
    float mean = s * (1.f / D);
    float var  = ss * (1.f / D) - mean * mean;
    float rstd = rsqrtf(var + 1e-5f);
    float4 gv = ((const float4*)gw)[tid];
    float4 bv = ((const float4*)bw)[tid];
    float4 o4;
    o4.x = tf32r((v.x - mean) * rstd * gv.x + bv.x);
    o4.y = tf32r((v.y - mean) * rstd * gv.y + bv.y);
    o4.z = tf32r((v.z - mean) * rstd * gv.z + bv.z);
    o4.w = tf32r((v.w - mean) * rstd * gv.w + bv.w);
    ((float4*)(out + (size_t)row * D))[tid] = o4;
}

// ============== mma.sync tf32 GEMM (round-5 config + ldmatrix fragment loads) ==============
#define BM 128
#define BN 128
#define BK 32
#define LDT 36
#define TBUF (128 * LDT)
#define GSMEM (4 * TBUF * 4)     // 73728 B -> 3 CTAs/SM

template<int EPI>
__global__ __launch_bounds__(128) void tc_gemm(const float* __restrict__ A,
                                               const float* __restrict__ Bt,
                                               const float* __restrict__ bias,
                                               const float* __restrict__ res,
                                               float* __restrict__ C,
                                               int M, int N_, int K)
{
    extern __shared__ float smem[];
    float* AsBase = smem;
    float* BsBase = smem + 2 * TBUF;
    const int tid = threadIdx.x, lane = tid & 31, wid = tid >> 5;
    const int wm = (wid >> 1) * 64, wn = (wid & 1) * 64;
    const int bm = blockIdx.y * BM, bn = blockIdx.x * BN;
    const int nch = K / BK;
    // ldmatrix lane roles: m_ = matrix index group, r_ = row within matrix
    const int m_ = lane >> 3, r_ = lane & 7;

    const float* Ag = A  + (size_t)bm * K;
    const float* Bg = Bt + (size_t)bn * K;

    float acc[4][8][4];
    #pragma unroll
    for (int mf = 0; mf < 4; mf++)
        #pragma unroll
        for (int nf = 0; nf < 8; nf++)
            #pragma unroll
            for (int q = 0; q < 4; q++) acc[mf][nf][q] = 0.f;

    auto load_chunk = [&](int c, int buf) {
        float* dA = AsBase + buf * TBUF;
        float* dB = BsBase + buf * TBUF;
        const float* a0 = Ag + c * BK;
        const float* b0 = Bg + c * BK;
        #pragma unroll
        for (int i = 0; i < 8; i++) {
            int slot = i * 128 + tid;
            int r = slot >> 3, u = slot & 7;
            cp16(smem_u32(dA + r * LDT + u * 4), a0 + (size_t)r * K + u * 4);
            cp16(smem_u32(dB + r * LDT + u * 4), b0 + (size_t)r * K + u * 4);
        }
        asm volatile("cp.async.commit_group;" ::: "memory");
    };

    load_chunk(0, 0);

    for (int c = 0; c < nch; c++) {
        if (c + 1 < nch) {
            load_chunk(c + 1, (c + 1) & 1);
            asm volatile("cp.async.wait_group 1;" ::: "memory");
        } else {
            asm volatile("cp.async.wait_group 0;" ::: "memory");
        }
        __syncthreads();
        const float* cA = AsBase + (c & 1) * TBUF;
        const float* cB = BsBase + (c & 1) * TBUF;
        #pragma unroll
        for (int ks = 0; ks < 4; ks++) {
            const int k0 = ks * 8;
            uint32_t a[4][4], b[8][2];
            // A frags: one ldmatrix.x4 per mf.
            // matrix order a0..a3 = [rows+0,k+0],[rows+8,k+0],[rows+0,k+4],[rows+8,k+4]
            #pragma unroll
            for (int mf = 0; mf < 4; mf++) {
                const float* p = cA + (wm + mf * 16 + (m_ & 1) * 8 + r_) * LDT
                               + k0 + (m_ >> 1) * 4;
                ldsm4(a[mf][0], a[mf][1], a[mf][2], a[mf][3], p);
            }
            // B frags: one ldmatrix.x4 per nf-pair.
            // matrix order = b[nf][0], b[nf][1], b[nf+1][0], b[nf+1][1]
            #pragma unroll
            for (int nfp = 0; nfp < 4; nfp++) {
                const float* p = cB + (wn + (nfp * 2 + (m_ >> 1)) * 8 + r_) * LDT
                               + k0 + (m_ & 1) * 4;
                ldsm4(b[nfp * 2][0], b[nfp * 2][1], b[nfp * 2 + 1][0], b[nfp * 2 + 1][1], p);
            }
            #pragma unroll
            for (int mf = 0; mf < 4; mf++)
                #pragma unroll
                for (int nf = 0; nf < 8; nf++)
                    mma_tf32(acc[mf][nf], a[mf], b[nf]);
        }
        __syncthreads();
    }

    const float GC = 0.7978845608028654f;
    #pragma unroll
    for (int mf = 0; mf < 4; mf++) {
        #pragma unroll
        for (int half = 0; half < 2; half++) {
            int row = bm + wm + mf * 16 + (lane >> 2) + half * 8;
            float* Crow = C + (size_t)row * N_ + bn + wn;
            const float* Rrow = res + (size_t)row * N_ + bn + wn;
            #pragma unroll
            for (int nf = 0; nf < 8; nf++) {
                int col = nf * 8 + 2 * (lane & 3);
                float2 v;
                v.x = acc[mf][nf][half * 2 + 0] + bias[bn + wn + col];
                v.y = acc[mf][nf][half * 2 + 1] + bias[bn + wn + col + 1];
                if (EPI == 1) {
                    v.x = tf32r(0.5f * v.x * (1.f + tanhf(GC * (v.x + 0.044715f * v.x * v.x * v.x))));
                    v.y = tf32r(0.5f * v.y * (1.f + tanhf(GC * (v.y + 0.044715f * v.y * v.y * v.y))));
                }
                if (EPI == 2) {
                    float2 rv = *(const float2*)(Rrow + col);
                    v.x += rv.x; v.y += rv.y;
                }
                *(float2*)(Crow + col) = v;
            }
        }
    }
}

// ============== Flash attention (causal) with tf32 mma.sync (round-5 proven config) ==============
// Q-tile 128 (4 warps x 32 rows), K-tile 64, DH=64. cp.async double-buffered K/V.
#define AST 68
#define ASMEM ((2 * 128 + 4 * 64) * AST * 4)   // 139264 B

__global__ __launch_bounds__(128) void attn_kernel(const float* __restrict__ qkv,
                                                   float* __restrict__ out)
{
    extern __shared__ float smem[];
    float* Qs  = smem;                        // 128 x AST
    float* Ps  = Qs  + 128 * AST;             // 128 x AST
    float* KsB = Ps  + 128 * AST;             // 2 x 64 x AST
    float* VsB = KsB + 2 * 64 * AST;          // 2 x 64 x AST

    const int b = blockIdx.z, h = blockIdx.y, q0 = blockIdx.x << 7;
    const int tid = threadIdx.x, lane = tid & 31, wid = tid >> 5;
    const int wm = wid * 32;
    const int lp = lane >> 2, lq = lane & 3;
    const size_t base = (size_t)b * SEQ * (3 * D) + h * DH;

    for (int s = tid; s < 2048; s += 128) {
        int r = s >> 4, u = s & 15;
        float4 v = *(const float4*)(qkv + base + (size_t)(q0 + r) * (3 * D) + u * 4);
        float* dst = Qs + r * AST + u * 4;
        dst[0] = tf32r(v.x * 0.125f); dst[1] = tf32r(v.y * 0.125f);
        dst[2] = tf32r(v.z * 0.125f); dst[3] = tf32r(v.w * 0.125f);
    }

    auto load_kv = [&](int kt, int buf) {
        float* dK = KsB + buf * 64 * AST;
        float* dV = VsB + buf * 64 * AST;
        const int k0 = kt << 6;
        #pragma unroll
        for (int i = 0; i < 8; i++) {
            int s = i * 128 + tid;
            int r = s >> 4, u = s & 15;
            const float* p = qkv + base + (size_t)(k0 + r) * (3 * D) + u * 4;
            cp16(smem_u32(dK + r * AST + u * 4), p + D);
            cp16(smem_u32(dV + r * AST + u * 4), p + 2 * D);
        }
        asm volatile("cp.async.commit_group;" ::: "memory");
    };

    float m_i[2][2], l_i[2][2], ao[2][8][4];
    #pragma unroll
    for (int mf = 0; mf < 2; mf++)
        #pragma unroll
        for (int hf = 0; hf < 2; hf++) { m_i[mf][hf] = -1e30f; l_i[mf][hf] = 0.f; }
    #pragma unroll
    for (int mf = 0; mf < 2; mf++)
        #pragma unroll
        for (int nf = 0; nf < 8; nf++)
            #pragma unroll
            for (int q = 0; q < 4; q++) ao[mf][nf][q] = 0.f;

    const int ntiles = (q0 >> 6) + 2;
    load_kv(0, 0);
    __syncthreads();

    for (int kt = 0; kt < ntiles; kt++) {
        const int buf = kt & 1;
        const int k0 = kt << 6;
        if (kt + 1 < ntiles) {
            load_kv(kt + 1, buf ^ 1);
            asm volatile("cp.async.wait_group 1;" ::: "memory");
        } else {
            asm volatile("cp.async.wait_group 0;" ::: "memory");
        }
        __syncthreads();
        const float* Ks = KsB + buf * 64 * AST;
        const float* Vs = VsB + buf * 64 * AST;

        float sc[2][8][4];
        #pragma unroll
        for (int mf = 0; mf < 2; mf++)
            #pragma unroll
            for (int nf = 0; nf < 8; nf++)
                #pragma unroll
                for (int q = 0; q < 4; q++) sc[mf][nf][q] = 0.f;
        #pragma unroll
        for (int kc = 0; kc < 8; kc++) {
            const int kk = kc * 8 + lq;
            uint32_t a[2][4], bfr[8][2];
            #pragma unroll
            for (int mf = 0; mf < 2; mf++) {
                const float* p = Qs + (wm + mf * 16 + lp) * AST + kk;
                a[mf][0] = __float_as_uint(p[0]);
                a[mf][1] = __float_as_uint(p[8 * AST]);
                a[mf][2] = __float_as_uint(p[4]);
                a[mf][3] = __float_as_uint(p[8 * AST + 4]);
            }
            #pragma unroll
            for (int nf = 0; nf < 8; nf++) {
                const float* p = Ks + (nf * 8 + lp) * AST + kk;
                bfr[nf][0] = __float_as_uint(p[0]);
                bfr[nf][1] = __float_as_uint(p[4]);
            }
            #pragma unroll
            for (int mf = 0; mf < 2; mf++)
                #pragma unroll
                for (int nf = 0; nf < 8; nf++)
                    mma_tf32(sc[mf][nf], a[mf], bfr[nf]);
        }

        if (kt >= ntiles - 2) {
            #pragma unroll
            for (int mf = 0; mf < 2; mf++)
                #pragma unroll
                for (int hf = 0; hf < 2; hf++) {
                    int row = q0 + wm + mf * 16 + lp + hf * 8;
                    #pragma unroll
                    for (int nf = 0; nf < 8; nf++) {
                        int col = k0 + nf * 8 + 2 * lq;
                        if (col > row)     sc[mf][nf][hf * 2 + 0] = -10000.0f;
                        if (col + 1 > row) sc[mf][nf][hf * 2 + 1] = -10000.0f;
                    }
                }
        }

        #pragma unroll
        for (int mf = 0; mf < 2; mf++)
            #pragma unroll
            for (int hf = 0; hf < 2; hf++) {
                float mx = sc[mf][0][hf * 2];
                #pragma unroll
                for (int nf = 0; nf < 8; nf++) {
                    mx = fmaxf(mx, sc[mf][nf][hf * 2 + 0]);
                    mx = fmaxf(mx, sc[mf][nf][hf * 2 + 1]);
                }
                mx = fmaxf(mx, __shfl_xor_sync(0xffffffffu, mx, 1, 4));
                mx = fmaxf(mx, __shfl_xor_sync(0xffffffffu, mx, 2, 4));
                float mnew = fmaxf(m_i[mf][hf], mx);
                float corr = __expf(m_i[mf][hf] - mnew);
                float sum = 0.f;
                #pragma unroll
                for (int nf = 0; nf < 8; nf++) {
                    float p0 = __expf(sc[mf][nf][hf * 2 + 0] - mnew);
                    float p1 = __expf(sc[mf][nf][hf * 2 + 1] - mnew);
                    sc[mf][nf][hf * 2 + 0] = p0;
                    sc[mf][nf][hf * 2 + 1] = p1;
                    sum += p0 + p1;
                }
                sum += __shfl_xor_sync(0xffffffffu, sum, 1, 4);
                sum += __shfl_xor_sync(0xffffffffu, sum, 2, 4);
                l_i[mf][hf] = l_i[mf][hf] * corr + sum;
                m_i[mf][hf] = mnew;
                #pragma unroll
                for (int nf = 0; nf < 8; nf++) {
                    ao[mf][nf][hf * 2 + 0] *= corr;
                    ao[mf][nf][hf * 2 + 1] *= corr;
                }
            }

        #pragma unroll
        for (int mf = 0; mf < 2; mf++) {
            int row0 = wm + mf * 16 + lp;
            #pragma unroll
            for (int nf = 0; nf < 8; nf++) {
                int col = nf * 8 + 2 * lq;
                *(float2*)(Ps + row0 * AST + col)       = make_float2(sc[mf][nf][0], sc[mf][nf][1]);
                *(float2*)(Ps + (row0 + 8) * AST + col) = make_float2(sc[mf][nf][2], sc[mf][nf][3]);
            }
        }
        __syncwarp();

        #pragma unroll
        for (int kc = 0; kc < 8; kc++) {
            const int kk = kc * 8 + lq;
            uint32_t a[2][4], bfr[8][2];
            #pragma unroll
            for (int mf = 0; mf < 2; mf++) {
                const float* p = Ps + (wm + mf * 16 + lp) * AST + kk;
                a[mf][0] = __float_as_uint(p[0]);
                a[mf][1] = __float_as_uint(p[8 * AST]);
                a[mf][2] = __float_as_uint(p[4]);
                a[mf][3] = __float_as_uint(p[8 * AST + 4]);
            }
            #pragma unroll
            for (int nf = 0; nf < 8; nf++) {
                const float* p0 = Vs + kk * AST + nf * 8 + lp;
                const float* p1 = Vs + (kk + 4) * AST + nf * 8 + lp;
                bfr[nf][0] = __float_as_uint(p0[0]);
                bfr[nf][1] = __float_as_uint(p1[0]);
            }
            #pragma unroll
            for (int mf = 0; mf < 2; mf++)
                #pragma unroll
                for (int nf = 0; nf < 8; nf++)
                    mma_tf32(ao[mf][nf], a[mf], bfr[nf]);
        }
        __syncthreads();
    }

    #pragma unroll
    for (int mf = 0; mf < 2; mf++)
        #pragma unroll
        for (int hf = 0; hf < 2; hf++) {
            float inv = 1.f / l_i[mf][hf];
            int row = q0 + wm + mf * 16 + lp + hf * 8;
            float* orow = out + (size_t)(b * SEQ + row) * D + h * DH;
            #pragma unroll
            for (int nf = 0; nf < 8; nf++) {
                int col = nf * 8 + 2 * lq;
                *(float2*)(orow + col) = make_float2(tf32r(ao[mf][nf][hf * 2 + 0] * inv),
                                                     tf32r(ao[mf][nf][hf * 2 + 1] * inv));
            }
        }
}

// ---------------- launch ----------------
extern "C" void kernel_launch(void* const* d_in, const int* in_sizes, int n_in,
                              void* d_out, int out_size)
{
    const float* hs    = (const float*)d_in[0];
    const float* ln1g  = (const float*)d_in[1];
    const float* ln1b  = (const float*)d_in[2];
    const float* wattn = (const float*)d_in[3];
    const float* battn = (const float*)d_in[4];
    const float* wproj = (const float*)d_in[5];
    const float* bproj = (const float*)d_in[6];
    const float* ln2g  = (const float*)d_in[7];
    const float* ln2b  = (const float*)d_in[8];
    const float* wfc   = (const float*)d_in[9];
    const float* bfc   = (const float*)d_in[10];
    const float* wmlp  = (const float*)d_in[11];
    const float* bmlp  = (const float*)d_in[12];
    float* out = (float*)d_out;

    int tokens = in_sizes[0] / D;   // 8192
    int B = tokens / SEQ;

    float *xln, *qkvb, *attnb, *resb, *mlnb, *fcb;
    float *wattn_t, *wproj_t, *wfc_t, *wmlp_t;
    cudaGetSymbolAddress((void**)&xln,   g_xln);
    cudaGetSymbolAddress((void**)&qkvb,  g_qkv);
    cudaGetSymbolAddress((void**)&attnb, g_attn);
    cudaGetSymbolAddress((void**)&resb,  g_res);
    cudaGetSymbolAddress((void**)&mlnb,  g_mln);
    cudaGetSymbolAddress((void**)&fcb,   g_fc);
    cudaGetSymbolAddress((void**)&wattn_t, g_wattn_t);
    cudaGetSymbolAddress((void**)&wproj_t, g_wproj_t);
    cudaGetSymbolAddress((void**)&wfc_t,   g_wfc_t);
    cudaGetSymbolAddress((void**)&wmlp_t,  g_wmlp_t);

    cudaFuncSetAttribute(tc_gemm<0>, cudaFuncAttributeMaxDynamicSharedMemorySize, GSMEM);
    cudaFuncSetAttribute(tc_gemm<1>, cudaFuncAttributeMaxDynamicSharedMemorySize, GSMEM);
    cudaFuncSetAttribute(tc_gemm<2>, cudaFuncAttributeMaxDynamicSharedMemorySize, GSMEM);
    cudaFuncSetAttribute(attn_kernel, cudaFuncAttributeMaxDynamicSharedMemorySize, ASMEM);

    // weight transposes (Bt[N][K] K-major, tf32-rounded)
    transpose_kernel<<<dim3(3 * D / 32, D / 32), 256>>>(wattn, wattn_t, D, 3 * D);
    transpose_kernel<<<dim3(D / 32, D / 32), 256>>>(wproj, wproj_t, D, D);
    transpose_kernel<<<dim3(FF / 32, D / 32), 256>>>(wfc, wfc_t, D, FF);
    transpose_kernel<<<dim3(D / 32, FF / 32), 256>>>(wmlp, wmlp_t, FF, D);

    // LN1
    ln_kernel<<<tokens, 256>>>(hs, ln1g, ln1b, xln);

    // QKV = xln @ w_attn + b_attn
    tc_gemm<0><<<dim3(3 * D / BN, tokens / BM), 128, GSMEM>>>(
        xln, wattn_t, battn, nullptr, qkvb, tokens, 3 * D, D);

    // attention (tf32 mma flash attention)
    attn_kernel<<<dim3(SEQ / 128, H, B), 128, ASMEM>>>(qkvb, attnb);

    // resid = hs + attnb @ w_attn_proj + b_attn_proj
    tc_gemm<2><<<dim3(D / BN, tokens / BM), 128, GSMEM>>>(
        attnb, wproj_t, bproj, hs, resb, tokens, D, D);

    // LN2
    ln_kernel<<<tokens, 256>>>(resb, ln2g, ln2b, mlnb);

    // fc = gelu_new(mlnb @ w_fc + b_fc)
    tc_gemm<1><<<dim3(FF / BN, tokens / BM), 128, GSMEM>>>(
        mlnb, wfc_t, bfc, nullptr, fcb, tokens, FF, D);

    // out = resb + fcb @ w_mlp_proj + b_mlp_proj
    tc_gemm<2><<<dim3(D / BN, tokens / BM), 128, GSMEM>>>(
        fcb, wmlp_t, bmlp, resb, out, tokens, D, FF);
}

// round 10
// speedup vs baseline: 1.6529x; 1.0068x over previous
#include <cuda_runtime.h>
#include <cstdint>

// Problem constants
#define D   1024
#define H   16
#define DH  64
#define FF  4096
#define SEQ 2048
#define MAXTOK 8192   // B=4 * S=2048

// ---------------- scratch (static device globals; no allocation) ----------------
__device__ float g_xln [MAXTOK * D];
__device__ float g_qkv [MAXTOK * 3 * D];
__device__ float g_attn[MAXTOK * D];
__device__ float g_res [MAXTOK * D];
__device__ float g_mln [MAXTOK * D];
__device__ float g_fc  [(size_t)MAXTOK * FF];
__device__ float g_wattn_t[3 * D * D];
__device__ float g_wproj_t[D * D];
__device__ float g_wfc_t  [FF * D];
__device__ float g_wmlp_t [D * FF];

// ---------------- helpers ----------------
__device__ __forceinline__ uint32_t smem_u32(const void* p){
    uint32_t a;
    asm("{ .reg .u64 t; cvta.to.shared.u64 t, %1; cvt.u32.u64 %0, t; }" : "=r"(a) : "l"(p));
    return a;
}
__device__ __forceinline__ float tf32r(float x){
    uint32_t u; asm("cvt.rna.tf32.f32 %0, %1;" : "=r"(u) : "f"(x));
    return __uint_as_float(u);
}
__device__ __forceinline__ void mma_tf32(float* c, const uint32_t* a, const uint32_t* b){
    asm volatile(
        "mma.sync.aligned.m16n8k8.row.col.f32.tf32.tf32.f32 "
        "{%0,%1,%2,%3}, {%4,%5,%6,%7}, {%8,%9}, {%0,%1,%2,%3};\n"
        : "+f"(c[0]), "+f"(c[1]), "+f"(c[2]), "+f"(c[3])
        : "r"(a[0]), "r"(a[1]), "r"(a[2]), "r"(a[3]), "r"(b[0]), "r"(b[1]));
}
__device__ __forceinline__ void ldsm4(uint32_t& r0, uint32_t& r1, uint32_t& r2, uint32_t& r3,
                                      const void* p){
    asm volatile("ldmatrix.sync.aligned.m8n8.x4.shared.b16 {%0,%1,%2,%3}, [%4];"
        : "=r"(r0), "=r"(r1), "=r"(r2), "=r"(r3) : "r"(smem_u32(p)));
}
__device__ __forceinline__ void cp16(uint32_t smem_addr, const void* gptr){
    asm volatile("cp.async.cg.shared.global [%0], [%1], 16;" :: "r"(smem_addr), "l"(gptr));
}
// fast gelu_new: 0.5x(1+tanh(z)) = x*t/(t+1), t=exp(2z)
__device__ __forceinline__ float gelu_fast(float x){
    const float GC = 0.7978845608028654f;
    float z = GC * (x + 0.044715f * x * x * x);
    float t = __expf(2.f * z);
    return x * t / (t + 1.f);
}

// ---------------- transpose: in[R][C] -> out[C][R], rounded to tf32 ----------------
__global__ __launch_bounds__(256) void transpose_kernel(const float* __restrict__ in,
                                                        float* __restrict__ out, int R, int C)
{
    __shared__ float t[32][33];
    int bx = blockIdx.x * 32, by = blockIdx.y * 32;
    int x = threadIdx.x & 31, y0 = threadIdx.x >> 5;
    #pragma unroll
    for (int yy = y0; yy < 32; yy += 8)
        t[yy][x] = in[(size_t)(by + yy) * C + bx + x];
    __syncthreads();
    #pragma unroll
    for (int yy = y0; yy < 32; yy += 8)
        out[(size_t)(bx + yy) * R + by + x] = tf32r(t[x][yy]);
}

// ---------------- LayerNorm (output rounded to tf32: feeds GEMM A) ----------------
__global__ __launch_bounds__(256) void ln_kernel(const float* __restrict__ in,
                                                 const float* __restrict__ gw,
                                                 const float* __restrict__ bw,
                                                 float* __restrict__ out)
{
    __shared__ float red0[8], red1[8];
    int row = blockIdx.x, tid = threadIdx.x;
    const float4* x4 = (const float4*)(in + (size_t)row * D);
    float4 v = x4[tid];
    float s  = v.x + v.y + v.z + v.w;
    float ss = v.x*v.x + v.y*v.y + v.z*v.z + v.w*v.w;
    #pragma unroll
    for (int o = 16; o; o >>= 1) {
        s  += __shfl_xor_sync(0xffffffffu, s,  o);
        ss += __shfl_xor_sync(0xffffffffu, ss, o);
    }
    if ((tid & 31) == 0) { red0[tid >> 5] = s; red1[tid >> 5] = ss; }
    __syncthreads();
    s = 0.f; ss = 0.f;
    #pragma unroll
    for (int i = 0; i < 8; i++) { s += red0[i]; ss += red1[i]; }
    float mean = s * (1.f / D);
    float var  = ss * (1.f / D) - mean * mean;
    float rstd = rsqrtf(var + 1e-5f);
    float4 gv = ((const float4*)gw)[tid];
    float4 bv = ((const float4*)bw)[tid];
    float4 o4;
    o4.x = tf32r((v.x - mean) * rstd * gv.x + bv.x);
    o4.y = tf32r((v.y - mean) * rstd * gv.y + bv.y);
    o4.z = tf32r((v.z - mean) * rstd * gv.z + bv.z);
    o4.w = tf32r((v.w - mean) * rstd * gv.w + bv.w);
    ((float4*)(out + (size_t)row * D))[tid] = o4;
}

// ============== mma.sync tf32 GEMM: ldmatrix frags + single barrier per chunk ==============
#define BM 128
#define BN 128
#define BK 32
#define LDT 36
#define TBUF (128 * LDT)
#define GSMEM (4 * TBUF * 4)     // 73728 B -> 3 CTAs/SM

template<int EPI>
__global__ __launch_bounds__(128) void tc_gemm(const float* __restrict__ A,
                                               const float* __restrict__ Bt,
                                               const float* __restrict__ bias,
                                               const float* __restrict__ res,
                                               float* __restrict__ C,
                                               int M, int N_, int K)
{
    extern __shared__ float smem[];
    float* AsBase = smem;
    float* BsBase = smem + 2 * TBUF;
    const int tid = threadIdx.x, lane = tid & 31, wid = tid >> 5;
    const int wm = (wid >> 1) * 64, wn = (wid & 1) * 64;
    const int bm = blockIdx.y * BM, bn = blockIdx.x * BN;
    const int nch = K / BK;
    const int m_ = lane >> 3, r_ = lane & 7;

    const float* Ag = A  + (size_t)bm * K;
    const float* Bg = Bt + (size_t)bn * K;

    float acc[4][8][4];
    #pragma unroll
    for (int mf = 0; mf < 4; mf++)
        #pragma unroll
        for (int nf = 0; nf < 8; nf++)
            #pragma unroll
            for (int q = 0; q < 4; q++) acc[mf][nf][q] = 0.f;

    auto load_chunk = [&](int c, int buf) {
        float* dA = AsBase + buf * TBUF;
        float* dB = BsBase + buf * TBUF;
        const float* a0 = Ag + c * BK;
        const float* b0 = Bg + c * BK;
        #pragma unroll
        for (int i = 0; i < 8; i++) {
            int slot = i * 128 + tid;
            int r = slot >> 3, u = slot & 7;
            cp16(smem_u32(dA + r * LDT + u * 4), a0 + (size_t)r * K + u * 4);
            cp16(smem_u32(dB + r * LDT + u * 4), b0 + (size_t)r * K + u * 4);
        }
        asm volatile("cp.async.commit_group;" ::: "memory");
    };

    load_chunk(0, 0);

    for (int c = 0; c < nch; c++) {
        asm volatile("cp.async.wait_group 0;" ::: "memory");  // only chunk c in flight here
        __syncthreads();   // (a) chunk c visible to all  (b) all done reading slot (c+1)&1
        if (c + 1 < nch) load_chunk(c + 1, (c + 1) & 1);

        const float* cA = AsBase + (c & 1) * TBUF;
        const float* cB = BsBase + (c & 1) * TBUF;
        #pragma unroll
        for (int ks = 0; ks < 4; ks++) {
            const int k0 = ks * 8;
            uint32_t a[4][4], b[8][2];
            #pragma unroll
            for (int mf = 0; mf < 4; mf++) {
                const float* p = cA + (wm + mf * 16 + (m_ & 1) * 8 + r_) * LDT
                               + k0 + (m_ >> 1) * 4;
                ldsm4(a[mf][0], a[mf][1], a[mf][2], a[mf][3], p);
            }
            #pragma unroll
            for (int nfp = 0; nfp < 4; nfp++) {
                const float* p = cB + (wn + (nfp * 2 + (m_ >> 1)) * 8 + r_) * LDT
                               + k0 + (m_ & 1) * 4;
                ldsm4(b[nfp * 2][0], b[nfp * 2][1], b[nfp * 2 + 1][0], b[nfp * 2 + 1][1], p);
            }
            #pragma unroll
            for (int mf = 0; mf < 4; mf++)
                #pragma unroll
                for (int nf = 0; nf < 8; nf++)
                    mma_tf32(acc[mf][nf], a[mf], b[nf]);
        }
    }

    #pragma unroll
    for (int mf = 0; mf < 4; mf++) {
        #pragma unroll
        for (int half = 0; half < 2; half++) {
            int row = bm + wm + mf * 16 + (lane >> 2) + half * 8;
            float* Crow = C + (size_t)row * N_ + bn + wn;
            const float* Rrow = res + (size_t)row * N_ + bn + wn;
            #pragma unroll
            for (int nf = 0; nf < 8; nf++) {
                int col = nf * 8 + 2 * (lane & 3);
                float2 v;
                v.x = acc[mf][nf][half * 2 + 0] + bias[bn + wn + col];
                v.y = acc[mf][nf][half * 2 + 1] + bias[bn + wn + col + 1];
                if (EPI == 1) {
                    v.x = tf32r(gelu_fast(v.x));
                    v.y = tf32r(gelu_fast(v.y));
                }
                if (EPI == 2) {
                    float2 rv = *(const float2*)(Rrow + col);
                    v.x += rv.x; v.y += rv.y;
                }
                *(float2*)(Crow + col) = v;
            }
        }
    }
}

// ============== Flash attention (causal), tf32 mma + ldmatrix, single barrier ==============
// Q-tile 128 (4 warps x 32 rows), K-tile 64, DH=64. cp.async double-buffered K/V.
#define AST 68
#define ASMEM ((2 * 128 + 4 * 64) * AST * 4)   // 139264 B

__global__ __launch_bounds__(128) void attn_kernel(const float* __restrict__ qkv,
                                                   float* __restrict__ out)
{
    extern __shared__ float smem[];
    float* Qs  = smem;                        // 128 x AST
    float* Ps  = Qs  + 128 * AST;             // 128 x AST
    float* KsB = Ps  + 128 * AST;             // 2 x 64 x AST
    float* VsB = KsB + 2 * 64 * AST;          // 2 x 64 x AST

    const int b = blockIdx.z, h = blockIdx.y, q0 = blockIdx.x << 7;
    const int tid = threadIdx.x, lane = tid & 31, wid = tid >> 5;
    const int wm = wid * 32;
    const int lp = lane >> 2, lq = lane & 3;
    const int m_ = lane >> 3, r_ = lane & 7;
    const size_t base = (size_t)b * SEQ * (3 * D) + h * DH;

    for (int s = tid; s < 2048; s += 128) {
        int r = s >> 4, u = s & 15;
        float4 v = *(const float4*)(qkv + base + (size_t)(q0 + r) * (3 * D) + u * 4);
        float* dst = Qs + r * AST + u * 4;
        dst[0] = tf32r(v.x * 0.125f); dst[1] = tf32r(v.y * 0.125f);
        dst[2] = tf32r(v.z * 0.125f); dst[3] = tf32r(v.w * 0.125f);
    }

    auto load_kv = [&](int kt, int buf) {
        float* dK = KsB + buf * 64 * AST;
        float* dV = VsB + buf * 64 * AST;
        const int k0 = kt << 6;
        #pragma unroll
        for (int i = 0; i < 8; i++) {
            int s = i * 128 + tid;
            int r = s >> 4, u = s & 15;
            const float* p = qkv + base + (size_t)(k0 + r) * (3 * D) + u * 4;
            cp16(smem_u32(dK + r * AST + u * 4), p + D);
            cp16(smem_u32(dV + r * AST + u * 4), p + 2 * D);
        }
        asm volatile("cp.async.commit_group;" ::: "memory");
    };

    float m_i[2][2], l_i[2][2], ao[2][8][4];
    #pragma unroll
    for (int mf = 0; mf < 2; mf++)
        #pragma unroll
        for (int hf = 0; hf < 2; hf++) { m_i[mf][hf] = -1e30f; l_i[mf][hf] = 0.f; }
    #pragma unroll
    for (int mf = 0; mf < 2; mf++)
        #pragma unroll
        for (int nf = 0; nf < 8; nf++)
            #pragma unroll
            for (int q = 0; q < 4; q++) ao[mf][nf][q] = 0.f;

    const int ntiles = (q0 >> 6) + 2;
    load_kv(0, 0);

    for (int kt = 0; kt < ntiles; kt++) {
        const int buf = kt & 1;
        const int k0 = kt << 6;
        asm volatile("cp.async.wait_group 0;" ::: "memory");   // tile kt landed
        __syncthreads();   // visible to all; all done reading buf^1 (read during kt-1)
        if (kt + 1 < ntiles) load_kv(kt + 1, buf ^ 1);
        const float* Ks = KsB + buf * 64 * AST;
        const float* Vs = VsB + buf * 64 * AST;

        // ---- S = Q K^T (ldmatrix frags) ----
        float sc[2][8][4];
        #pragma unroll
        for (int mf = 0; mf < 2; mf++)
            #pragma unroll
            for (int nf = 0; nf < 8; nf++)
                #pragma unroll
                for (int q = 0; q < 4; q++) sc[mf][nf][q] = 0.f;
        #pragma unroll
        for (int kc = 0; kc < 8; kc++) {
            const int k0f = kc * 8;
            uint32_t a[2][4], bfr[8][2];
            #pragma unroll
            for (int mf = 0; mf < 2; mf++) {
                const float* p = Qs + (wm + mf * 16 + (m_ & 1) * 8 + r_) * AST
                               + k0f + (m_ >> 1) * 4;
                ldsm4(a[mf][0], a[mf][1], a[mf][2], a[mf][3], p);
            }
            #pragma unroll
            for (int nfp = 0; nfp < 4; nfp++) {
                const float* p = Ks + ((nfp * 2 + (m_ >> 1)) * 8 + r_) * AST
                               + k0f + (m_ & 1) * 4;
                ldsm4(bfr[nfp * 2][0], bfr[nfp * 2][1], bfr[nfp * 2 + 1][0], bfr[nfp * 2 + 1][1], p);
            }
            #pragma unroll
            for (int mf = 0; mf < 2; mf++)
                #pragma unroll
                for (int nf = 0; nf < 8; nf++)
                    mma_tf32(sc[mf][nf], a[mf], bfr[nf]);
        }

        if (kt >= ntiles - 2) {
            #pragma unroll
            for (int mf = 0; mf < 2; mf++)
                #pragma unroll
                for (int hf = 0; hf < 2; hf++) {
                    int row = q0 + wm + mf * 16 + lp + hf * 8;
                    #pragma unroll
                    for (int nf = 0; nf < 8; nf++) {
                        int col = k0 + nf * 8 + 2 * lq;
                        if (col > row)     sc[mf][nf][hf * 2 + 0] = -10000.0f;
                        if (col + 1 > row) sc[mf][nf][hf * 2 + 1] = -10000.0f;
                    }
                }
        }

        #pragma unroll
        for (int mf = 0; mf < 2; mf++)
            #pragma unroll
            for (int hf = 0; hf < 2; hf++) {
                float mx = sc[mf][0][hf * 2];
                #pragma unroll
                for (int nf = 0; nf < 8; nf++) {
                    mx = fmaxf(mx, sc[mf][nf][hf * 2 + 0]);
                    mx = fmaxf(mx, sc[mf][nf][hf * 2 + 1]);
                }
                mx = fmaxf(mx, __shfl_xor_sync(0xffffffffu, mx, 1, 4));
                mx = fmaxf(mx, __shfl_xor_sync(0xffffffffu, mx, 2, 4));
                float mnew = fmaxf(m_i[mf][hf], mx);
                float corr = __expf(m_i[mf][hf] - mnew);
                float sum = 0.f;
                #pragma unroll
                for (int nf = 0; nf < 8; nf++) {
                    float p0 = __expf(sc[mf][nf][hf * 2 + 0] - mnew);
                    float p1 = __expf(sc[mf][nf][hf * 2 + 1] - mnew);
                    sc[mf][nf][hf * 2 + 0] = p0;
                    sc[mf][nf][hf * 2 + 1] = p1;
                    sum += p0 + p1;
                }
                sum += __shfl_xor_sync(0xffffffffu, sum, 1, 4);
                sum += __shfl_xor_sync(0xffffffffu, sum, 2, 4);
                l_i[mf][hf] = l_i[mf][hf] * corr + sum;
                m_i[mf][hf] = mnew;
                #pragma unroll
                for (int nf = 0; nf < 8; nf++) {
                    ao[mf][nf][hf * 2 + 0] *= corr;
                    ao[mf][nf][hf * 2 + 1] *= corr;
                }
            }

        #pragma unroll
        for (int mf = 0; mf < 2; mf++) {
            int row0 = wm + mf * 16 + lp;
            #pragma unroll
            for (int nf = 0; nf < 8; nf++) {
                int col = nf * 8 + 2 * lq;
                *(float2*)(Ps + row0 * AST + col)       = make_float2(sc[mf][nf][0], sc[mf][nf][1]);
                *(float2*)(Ps + (row0 + 8) * AST + col) = make_float2(sc[mf][nf][2], sc[mf][nf][3]);
            }
        }
        __syncwarp();

        // ---- O += P V : P via ldmatrix, V scalar (transposed role) ----
        #pragma unroll
        for (int kc = 0; kc < 8; kc++) {
            const int kk = kc * 8 + lq;
            uint32_t a[2][4], bfr[8][2];
            #pragma unroll
            for (int mf = 0; mf < 2; mf++) {
                const float* p = Ps + (wm + mf * 16 + (m_ & 1) * 8 + r_) * AST
                               + kc * 8 + (m_ >> 1) * 4;
                ldsm4(a[mf][0], a[mf][1], a[mf][2], a[mf][3], p);
            }
            #pragma unroll
            for (int nf = 0; nf < 8; nf++) {
                const float* p0 = Vs + kk * AST + nf * 8 + lp;
                const float* p1 = Vs + (kk + 4) * AST + nf * 8 + lp;
                bfr[nf][0] = __float_as_uint(p0[0]);
                bfr[nf][1] = __float_as_uint(p1[0]);
            }
            #pragma unroll
            for (int mf = 0; mf < 2; mf++)
                #pragma unroll
                for (int nf = 0; nf < 8; nf++)
                    mma_tf32(ao[mf][nf], a[mf], bfr[nf]);
        }
    }

    #pragma unroll
    for (int mf = 0; mf < 2; mf++)
        #pragma unroll
        for (int hf = 0; hf < 2; hf++) {
            float inv = 1.f / l_i[mf][hf];
            int row = q0 + wm + mf * 16 + lp + hf * 8;
            float* orow = out + (size_t)(b * SEQ + row) * D + h * DH;
            #pragma unroll
            for (int nf = 0; nf < 8; nf++) {
                int col = nf * 8 + 2 * lq;
                *(float2*)(orow + col) = make_float2(tf32r(ao[mf][nf][hf * 2 + 0] * inv),
                                                     tf32r(ao[mf][nf][hf * 2 + 1] * inv));
            }
        }
}

// ---------------- launch ----------------
extern "C" void kernel_launch(void* const* d_in, const int* in_sizes, int n_in,
                              void* d_out, int out_size)
{
    const float* hs    = (const float*)d_in[0];
    const float* ln1g  = (const float*)d_in[1];
    const float* ln1b  = (const float*)d_in[2];
    const float* wattn = (const float*)d_in[3];
    const float* battn = (const float*)d_in[4];
    const float* wproj = (const float*)d_in[5];
    const float* bproj = (const float*)d_in[6];
    const float* ln2g  = (const float*)d_in[7];
    const float* ln2b  = (const float*)d_in[8];
    const float* wfc   = (const float*)d_in[9];
    const float* bfc   = (const float*)d_in[10];
    const float* wmlp  = (const float*)d_in[11];
    const float* bmlp  = (const float*)d_in[12];
    float* out = (float*)d_out;

    int tokens = in_sizes[0] / D;   // 8192
    int B = tokens / SEQ;

    float *xln, *qkvb, *attnb, *resb, *mlnb, *fcb;
    float *wattn_t, *wproj_t, *wfc_t, *wmlp_t;
    cudaGetSymbolAddress((void**)&xln,   g_xln);
    cudaGetSymbolAddress((void**)&qkvb,  g_qkv);
    cudaGetSymbolAddress((void**)&attnb, g_attn);
    cudaGetSymbolAddress((void**)&resb,  g_res);
    cudaGetSymbolAddress((void**)&mlnb,  g_mln);
    cudaGetSymbolAddress((void**)&fcb,   g_fc);
    cudaGetSymbolAddress((void**)&wattn_t, g_wattn_t);
    cudaGetSymbolAddress((void**)&wproj_t, g_wproj_t);
    cudaGetSymbolAddress((void**)&wfc_t,   g_wfc_t);
    cudaGetSymbolAddress((void**)&wmlp_t,  g_wmlp_t);

    cudaFuncSetAttribute(tc_gemm<0>, cudaFuncAttributeMaxDynamicSharedMemorySize, GSMEM);
    cudaFuncSetAttribute(tc_gemm<1>, cudaFuncAttributeMaxDynamicSharedMemorySize, GSMEM);
    cudaFuncSetAttribute(tc_gemm<2>, cudaFuncAttributeMaxDynamicSharedMemorySize, GSMEM);
    cudaFuncSetAttribute(attn_kernel, cudaFuncAttributeMaxDynamicSharedMemorySize, ASMEM);

    // weight transposes (Bt[N][K] K-major, tf32-rounded)
    transpose_kernel<<<dim3(3 * D / 32, D / 32), 256>>>(wattn, wattn_t, D, 3 * D);
    transpose_kernel<<<dim3(D / 32, D / 32), 256>>>(wproj, wproj_t, D, D);
    transpose_kernel<<<dim3(FF / 32, D / 32), 256>>>(wfc, wfc_t, D, FF);
    transpose_kernel<<<dim3(D / 32, FF / 32), 256>>>(wmlp, wmlp_t, FF, D);

    // LN1
    ln_kernel<<<tokens, 256>>>(hs, ln1g, ln1b, xln);

    // QKV = xln @ w_attn + b_attn
    tc_gemm<0><<<dim3(3 * D / BN, tokens / BM), 128, GSMEM>>>(
        xln, wattn_t, battn, nullptr, qkvb, tokens, 3 * D, D);

    // attention (tf32 mma flash attention)
    attn_kernel<<<dim3(SEQ / 128, H, B), 128, ASMEM>>>(qkvb, attnb);

    // resid = hs + attnb @ w_attn_proj + b_attn_proj
    tc_gemm<2><<<dim3(D / BN, tokens / BM), 128, GSMEM>>>(
        attnb, wproj_t, bproj, hs, resb, tokens, D, D);

    // LN2
    ln_kernel<<<tokens, 256>>>(resb, ln2g, ln2b, mlnb);

    // fc = gelu_new(mlnb @ w_fc + b_fc)
    tc_gemm<1><<<dim3(FF / BN, tokens / BM), 128, GSMEM>>>(
        mlnb, wfc_t, bfc, nullptr, fcb, tokens, FF, D);

    // out = resb + fcb @ w_mlp_proj + b_mlp_proj
    tc_gemm<2><<<dim3(D / BN, tokens / BM), 128, GSMEM>>>(
        fcb, wmlp_t, bmlp, resb, out, tokens, D, FF);
}

// round 12
// speedup vs baseline: 1.7655x; 1.0681x over previous
#include <cuda_runtime.h>
#include <cstdint>

// Problem constants
#define D   1024
#define H   16
#define DH  64
#define FF  4096
#define SEQ 2048
#define MAXTOK 8192   // B=4 * S=2048

// ---------------- scratch (static device globals; no allocation) ----------------
__device__ float g_xln [MAXTOK * D];
__device__ float g_qkv [MAXTOK * 3 * D];
__device__ float g_attn[MAXTOK * D];
__device__ float g_res [MAXTOK * D];
__device__ float g_mln [MAXTOK * D];
__device__ float g_fc  [(size_t)MAXTOK * FF];
__device__ float g_wattn_t[3 * D * D];
__device__ float g_wproj_t[D * D];
__device__ float g_wfc_t  [FF * D];
__device__ float g_wmlp_t [D * FF];

// ---------------- helpers ----------------
__device__ __forceinline__ uint32_t smem_u32(const void* p){
    uint32_t a;
    asm("{ .reg .u64 t; cvta.to.shared.u64 t, %1; cvt.u32.u64 %0, t; }" : "=r"(a) : "l"(p));
    return a;
}
__device__ __forceinline__ float tf32r(float x){
    uint32_t u; asm("cvt.rna.tf32.f32 %0, %1;" : "=r"(u) : "f"(x));
    return __uint_as_float(u);
}
__device__ __forceinline__ void mma_tf32(float* c, const uint32_t* a, const uint32_t* b){
    asm volatile(
        "mma.sync.aligned.m16n8k8.row.col.f32.tf32.tf32.f32 "
        "{%0,%1,%2,%3}, {%4,%5,%6,%7}, {%8,%9}, {%0,%1,%2,%3};\n"
        : "+f"(c[0]), "+f"(c[1]), "+f"(c[2]), "+f"(c[3])
        : "r"(a[0]), "r"(a[1]), "r"(a[2]), "r"(a[3]), "r"(b[0]), "r"(b[1]));
}
__device__ __forceinline__ void ldsm4(uint32_t& r0, uint32_t& r1, uint32_t& r2, uint32_t& r3,
                                      const void* p){
    asm volatile("ldmatrix.sync.aligned.m8n8.x4.shared.b16 {%0,%1,%2,%3}, [%4];"
        : "=r"(r0), "=r"(r1), "=r"(r2), "=r"(r3) : "r"(smem_u32(p)));
}
__device__ __forceinline__ void cp16(uint32_t smem_addr, const void* gptr){
    asm volatile("cp.async.cg.shared.global [%0], [%1], 16;" :: "r"(smem_addr), "l"(gptr));
}
// fast gelu_new: 0.5x(1+tanh(z)) = x*t/(t+1), t=exp(2z)
__device__ __forceinline__ float gelu_fast(float x){
    const float GC = 0.7978845608028654f;
    float z = GC * (x + 0.044715f * x * x * x);
    float t = __expf(2.f * z);
    return x * t / (t + 1.f);
}

// ---------------- transpose: in[R][C] -> out[C][R], rounded to tf32 ----------------
__global__ __launch_bounds__(256) void transpose_kernel(const float* __restrict__ in,
                                                        float* __restrict__ out, int R, int C)
{
    __shared__ float t[32][33];
    int bx = blockIdx.x * 32, by = blockIdx.y * 32;
    int x = threadIdx.x & 31, y0 = threadIdx.x >> 5;
    #pragma unroll
    for (int yy = y0; yy < 32; yy += 8)
        t[yy][x] = in[(size_t)(by + yy) * C + bx + x];
    __syncthreads();
    #pragma unroll
    for (int yy = y0; yy < 32; yy += 8)
        out[(size_t)(bx + yy) * R + by + x] = tf32r(t[x][yy]);
}

// ---------------- LayerNorm (output rounded to tf32: feeds GEMM A) ----------------
__global__ __launch_bounds__(256) void ln_kernel(const float* __restrict__ in,
                                                 const float* __restrict__ gw,
                                                 const float* __restrict__ bw,
                                                 float* __restrict__ out)
{
    __shared__ float red0[8], red1[8];
    int row = blockIdx.x, tid = threadIdx.x;
    const float4* x4 = (const float4*)(in + (size_t)row * D);
    float4 v = x4[tid];
    float s  = v.x + v.y + v.z + v.w;
    float ss = v.x*v.x + v.y*v.y + v.z*v.z + v.w*v.w;
    #pragma unroll
    for (int o = 16; o; o >>= 1) {
        s  += __shfl_xor_sync(0xffffffffu, s,  o);
        ss += __shfl_xor_sync(0xffffffffu, ss, o);
    }
    if ((tid & 31) == 0) { red0[tid >> 5] = s; red1[tid >> 5] = ss; }
    __syncthreads();
    s = 0.f; ss = 0.f;
    #pragma unroll
    for (int i = 0; i < 8; i++) { s += red0[i]; ss += red1[i]; }
    float mean = s * (1.f / D);
    float var  = ss * (1.f / D) - mean * mean;
    float rstd = rsqrtf(var + 1e-5f);
    float4 gv = ((const float4*)gw)[tid];
    float4 bv = ((const float4*)bw)[tid];
    float4 o4;
    o4.x = tf32r((v.x - mean) * rstd * gv.x + bv.x);
    o4.y = tf32r((v.y - mean) * rstd * gv.y + bv.y);
    o4.z = tf32r((v.z - mean) * rstd * gv.z + bv.z);
    o4.w = tf32r((v.w - mean) * rstd * gv.w + bv.w);
    ((float4*)(out + (size_t)row * D))[tid] = o4;
}

// ============== mma.sync tf32 GEMM: ldmatrix frags + single barrier per chunk ==============
#define BM 128
#define BN 128
#define BK 32
#define LDT 36
#define TBUF (128 * LDT)
#define GSMEM (4 * TBUF * 4)     // 73728 B -> 3 CTAs/SM

template<int EPI>
__global__ __launch_bounds__(128) void tc_gemm(const float* __restrict__ A,
                                               const float* __restrict__ Bt,
                                               const float* __restrict__ bias,
                                               const float* __restrict__ res,
                                               float* __restrict__ C,
                                               int M, int N_, int K)
{
    extern __shared__ float smem[];
    float* AsBase = smem;
    float* BsBase = smem + 2 * TBUF;
    const int tid = threadIdx.x, lane = tid & 31, wid = tid >> 5;
    const int wm = (wid >> 1) * 64, wn = (wid & 1) * 64;
    const int bm = blockIdx.y * BM, bn = blockIdx.x * BN;
    const int nch = K / BK;
    const int m_ = lane >> 3, r_ = lane & 7;

    const float* Ag = A  + (size_t)bm * K;
    const float* Bg = Bt + (size_t)bn * K;

    float acc[4][8][4];
    #pragma unroll
    for (int mf = 0; mf < 4; mf++)
        #pragma unroll
        for (int nf = 0; nf < 8; nf++)
            #pragma unroll
            for (int q = 0; q < 4; q++) acc[mf][nf][q] = 0.f;

    auto load_chunk = [&](int c, int buf) {
        float* dA = AsBase + buf * TBUF;
        float* dB = BsBase + buf * TBUF;
        const float* a0 = Ag + c * BK;
        const float* b0 = Bg + c * BK;
        #pragma unroll
        for (int i = 0; i < 8; i++) {
            int slot = i * 128 + tid;
            int r = slot >> 3, u = slot & 7;
            cp16(smem_u32(dA + r * LDT + u * 4), a0 + (size_t)r * K + u * 4);
            cp16(smem_u32(dB + r * LDT + u * 4), b0 + (size_t)r * K + u * 4);
        }
        asm volatile("cp.async.commit_group;" ::: "memory");
    };

    load_chunk(0, 0);

    for (int c = 0; c < nch; c++) {
        asm volatile("cp.async.wait_group 0;" ::: "memory");
        __syncthreads();
        if (c + 1 < nch) load_chunk(c + 1, (c + 1) & 1);

        const float* cA = AsBase + (c & 1) * TBUF;
        const float* cB = BsBase + (c & 1) * TBUF;
        #pragma unroll
        for (int ks = 0; ks < 4; ks++) {
            const int k0 = ks * 8;
            uint32_t a[4][4], b[8][2];
            #pragma unroll
            for (int mf = 0; mf < 4; mf++) {
                const float* p = cA + (wm + mf * 16 + (m_ & 1) * 8 + r_) * LDT
                               + k0 + (m_ >> 1) * 4;
                ldsm4(a[mf][0], a[mf][1], a[mf][2], a[mf][3], p);
            }
            #pragma unroll
            for (int nfp = 0; nfp < 4; nfp++) {
                const float* p = cB + (wn + (nfp * 2 + (m_ >> 1)) * 8 + r_) * LDT
                               + k0 + (m_ & 1) * 4;
                ldsm4(b[nfp * 2][0], b[nfp * 2][1], b[nfp * 2 + 1][0], b[nfp * 2 + 1][1], p);
            }
            #pragma unroll
            for (int mf = 0; mf < 4; mf++)
                #pragma unroll
                for (int nf = 0; nf < 8; nf++)
                    mma_tf32(acc[mf][nf], a[mf], b[nf]);
        }
    }

    #pragma unroll
    for (int mf = 0; mf < 4; mf++) {
        #pragma unroll
        for (int half = 0; half < 2; half++) {
            int row = bm + wm + mf * 16 + (lane >> 2) + half * 8;
            float* Crow = C + (size_t)row * N_ + bn + wn;
            const float* Rrow = res + (size_t)row * N_ + bn + wn;
            #pragma unroll
            for (int nf = 0; nf < 8; nf++) {
                int col = nf * 8 + 2 * (lane & 3);
                float2 v;
                v.x = acc[mf][nf][half * 2 + 0] + bias[bn + wn + col];
                v.y = acc[mf][nf][half * 2 + 1] + bias[bn + wn + col + 1];
                if (EPI == 1) {
                    v.x = tf32r(gelu_fast(v.x));
                    v.y = tf32r(gelu_fast(v.y));
                }
                if (EPI == 2) {
                    float2 rv = *(const float2*)(Rrow + col);
                    v.x += rv.x; v.y += rv.y;
                }
                *(float2*)(Crow + col) = v;
            }
        }
    }
}

// ============== Flash attention (causal), tf32 mma; P via shuffle (no Ps smem) ==============
// Q-tile 128 (4 warps x 32 rows), K-tile 64, DH=64. cp.async double-buffered K/V.
// smem = (128 + 2*64 + 2*64) * AST * 4 = 104448 B -> 2 CTAs/SM
#define AST 68
#define ASMEM ((128 + 4 * 64) * AST * 4)

__global__ __launch_bounds__(128) void attn_kernel(const float* __restrict__ qkv,
                                                   float* __restrict__ out)
{
    extern __shared__ float smem[];
    float* Qs  = smem;                        // 128 x AST
    float* KsB = Qs  + 128 * AST;             // 2 x 64 x AST
    float* VsB = KsB + 2 * 64 * AST;          // 2 x 64 x AST

    const int b = blockIdx.z, h = blockIdx.y, q0 = blockIdx.x << 7;
    const int tid = threadIdx.x, lane = tid & 31, wid = tid >> 5;
    const int wm = wid * 32;
    const int lp = lane >> 2, lq = lane & 3;
    const int m_ = lane >> 3, r_ = lane & 7;
    const int psrc0 = (lane & 28) | (lq >> 1);   // quad-local shuffle sources
    const int psrc1 = psrc0 + 2;
    const bool podd = lq & 1;
    const size_t base = (size_t)b * SEQ * (3 * D) + h * DH;

    for (int s = tid; s < 2048; s += 128) {
        int r = s >> 4, u = s & 15;
        float4 v = *(const float4*)(qkv + base + (size_t)(q0 + r) * (3 * D) + u * 4);
        float* dst = Qs + r * AST + u * 4;
        dst[0] = tf32r(v.x * 0.125f); dst[1] = tf32r(v.y * 0.125f);
        dst[2] = tf32r(v.z * 0.125f); dst[3] = tf32r(v.w * 0.125f);
    }

    auto load_kv = [&](int kt, int buf) {
        float* dK = KsB + buf * 64 * AST;
        float* dV = VsB + buf * 64 * AST;
        const int k0 = kt << 6;
        #pragma unroll
        for (int i = 0; i < 8; i++) {
            int s = i * 128 + tid;
            int r = s >> 4, u = s & 15;
            const float* p = qkv + base + (size_t)(k0 + r) * (3 * D) + u * 4;
            cp16(smem_u32(dK + r * AST + u * 4), p + D);
            cp16(smem_u32(dV + r * AST + u * 4), p + 2 * D);
        }
        asm volatile("cp.async.commit_group;" ::: "memory");
    };

    float m_i[2][2], l_i[2][2], ao[2][8][4];
    #pragma unroll
    for (int mf = 0; mf < 2; mf++)
        #pragma unroll
        for (int hf = 0; hf < 2; hf++) { m_i[mf][hf] = -1e30f; l_i[mf][hf] = 0.f; }
    #pragma unroll
    for (int mf = 0; mf < 2; mf++)
        #pragma unroll
        for (int nf = 0; nf < 8; nf++)
            #pragma unroll
            for (int q = 0; q < 4; q++) ao[mf][nf][q] = 0.f;

    const int ntiles = (q0 >> 6) + 2;
    load_kv(0, 0);

    for (int kt = 0; kt < ntiles; kt++) {
        const int buf = kt & 1;
        const int k0 = kt << 6;
        asm volatile("cp.async.wait_group 0;" ::: "memory");
        __syncthreads();
        if (kt + 1 < ntiles) load_kv(kt + 1, buf ^ 1);
        const float* Ks = KsB + buf * 64 * AST;
        const float* Vs = VsB + buf * 64 * AST;

        // ---- S = Q K^T (ldmatrix frags) ----
        float sc[2][8][4];
        #pragma unroll
        for (int mf = 0; mf < 2; mf++)
            #pragma unroll
            for (int nf = 0; nf < 8; nf++)
                #pragma unroll
                for (int q = 0; q < 4; q++) sc[mf][nf][q] = 0.f;
        #pragma unroll
        for (int kc = 0; kc < 8; kc++) {
            const int k0f = kc * 8;
            uint32_t a[2][4], bfr[8][2];
            #pragma unroll
            for (int mf = 0; mf < 2; mf++) {
                const float* p = Qs + (wm + mf * 16 + (m_ & 1) * 8 + r_) * AST
                               + k0f + (m_ >> 1) * 4;
                ldsm4(a[mf][0], a[mf][1], a[mf][2], a[mf][3], p);
            }
            #pragma unroll
            for (int nfp = 0; nfp < 4; nfp++) {
                const float* p = Ks + ((nfp * 2 + (m_ >> 1)) * 8 + r_) * AST
                               + k0f + (m_ & 1) * 4;
                ldsm4(bfr[nfp * 2][0], bfr[nfp * 2][1], bfr[nfp * 2 + 1][0], bfr[nfp * 2 + 1][1], p);
            }
            #pragma unroll
            for (int mf = 0; mf < 2; mf++)
                #pragma unroll
                for (int nf = 0; nf < 8; nf++)
                    mma_tf32(sc[mf][nf], a[mf], bfr[nf]);
        }

        if (kt >= ntiles - 2) {
            #pragma unroll
            for (int mf = 0; mf < 2; mf++)
                #pragma unroll
                for (int hf = 0; hf < 2; hf++) {
                    int row = q0 + wm + mf * 16 + lp + hf * 8;
                    #pragma unroll
                    for (int nf = 0; nf < 8; nf++) {
                        int col = k0 + nf * 8 + 2 * lq;
                        if (col > row)     sc[mf][nf][hf * 2 + 0] = -10000.0f;
                        if (col + 1 > row) sc[mf][nf][hf * 2 + 1] = -10000.0f;
                    }
                }
        }

        #pragma unroll
        for (int mf = 0; mf < 2; mf++)
            #pragma unroll
            for (int hf = 0; hf < 2; hf++) {
                float mx = sc[mf][0][hf * 2];
                #pragma unroll
                for (int nf = 0; nf < 8; nf++) {
                    mx = fmaxf(mx, sc[mf][nf][hf * 2 + 0]);
                    mx = fmaxf(mx, sc[mf][nf][hf * 2 + 1]);
                }
                mx = fmaxf(mx, __shfl_xor_sync(0xffffffffu, mx, 1, 4));
                mx = fmaxf(mx, __shfl_xor_sync(0xffffffffu, mx, 2, 4));
                float mnew = fmaxf(m_i[mf][hf], mx);
                float corr = __expf(m_i[mf][hf] - mnew);
                float sum = 0.f;
                #pragma unroll
                for (int nf = 0; nf < 8; nf++) {
                    float p0 = __expf(sc[mf][nf][hf * 2 + 0] - mnew);
                    float p1 = __expf(sc[mf][nf][hf * 2 + 1] - mnew);
                    sc[mf][nf][hf * 2 + 0] = p0;
                    sc[mf][nf][hf * 2 + 1] = p1;
                    sum += p0 + p1;
                }
                sum += __shfl_xor_sync(0xffffffffu, sum, 1, 4);
                sum += __shfl_xor_sync(0xffffffffu, sum, 2, 4);
                l_i[mf][hf] = l_i[mf][hf] * corr + sum;
                m_i[mf][hf] = mnew;
                #pragma unroll
                for (int nf = 0; nf < 8; nf++) {
                    ao[mf][nf][hf * 2 + 0] *= corr;
                    ao[mf][nf][hf * 2 + 1] *= corr;
                }
            }

        // ---- O += P V : P A-frags built by intra-quad shuffles from C-frags ----
        // C-frag (row lp, cols 2lq..2lq+1); A-frag needs (row lp, col lq) & (col lq+4).
        #pragma unroll
        for (int kc = 0; kc < 8; kc++) {
            const int kk = kc * 8 + lq;
            uint32_t a[2][4], bfr[8][2];
            #pragma unroll
            for (int mf = 0; mf < 2; mf++) {
                float s00 = __shfl_sync(0xffffffffu, sc[mf][kc][0], psrc0);
                float s01 = __shfl_sync(0xffffffffu, sc[mf][kc][1], psrc0);
                float s20 = __shfl_sync(0xffffffffu, sc[mf][kc][2], psrc0);
                float s21 = __shfl_sync(0xffffffffu, sc[mf][kc][3], psrc0);
                float s02 = __shfl_sync(0xffffffffu, sc[mf][kc][0], psrc1);
                float s03 = __shfl_sync(0xffffffffu, sc[mf][kc][1], psrc1);
                float s22 = __shfl_sync(0xffffffffu, sc[mf][kc][2], psrc1);
                float s23 = __shfl_sync(0xffffffffu, sc[mf][kc][3], psrc1);
                a[mf][0] = __float_as_uint(podd ? s01 : s00);   // (lp,   kk)
                a[mf][1] = __float_as_uint(podd ? s21 : s20);   // (lp+8, kk)
                a[mf][2] = __float_as_uint(podd ? s03 : s02);   // (lp,   kk+4)
                a[mf][3] = __float_as_uint(podd ? s23 : s22);   // (lp+8, kk+4)
            }
            #pragma unroll
            for (int nf = 0; nf < 8; nf++) {
                const float* p0 = Vs + kk * AST + nf * 8 + lp;
                const float* p1 = Vs + (kk + 4) * AST + nf * 8 + lp;
                bfr[nf][0] = __float_as_uint(p0[0]);
                bfr[nf][1] = __float_as_uint(p1[0]);
            }
            #pragma unroll
            for (int mf = 0; mf < 2; mf++)
                #pragma unroll
                for (int nf = 0; nf < 8; nf++)
                    mma_tf32(ao[mf][nf], a[mf], bfr[nf]);
        }
    }

    #pragma unroll
    for (int mf = 0; mf < 2; mf++)
        #pragma unroll
        for (int hf = 0; hf < 2; hf++) {
            float inv = 1.f / l_i[mf][hf];
            int row = q0 + wm + mf * 16 + lp + hf * 8;
            float* orow = out + (size_t)(b * SEQ + row) * D + h * DH;
            #pragma unroll
            for (int nf = 0; nf < 8; nf++) {
                int col = nf * 8 + 2 * lq;
                *(float2*)(orow + col) = make_float2(tf32r(ao[mf][nf][hf * 2 + 0] * inv),
                                                     tf32r(ao[mf][nf][hf * 2 + 1] * inv));
            }
        }
}

// ---------------- launch ----------------
extern "C" void kernel_launch(void* const* d_in, const int* in_sizes, int n_in,
                              void* d_out, int out_size)
{
    const float* hs    = (const float*)d_in[0];
    const float* ln1g  = (const float*)d_in[1];
    const float* ln1b  = (const float*)d_in[2];
    const float* wattn = (const float*)d_in[3];
    const float* battn = (const float*)d_in[4];
    const float* wproj = (const float*)d_in[5];
    const float* bproj = (const float*)d_in[6];
    const float* ln2g  = (const float*)d_in[7];
    const float* ln2b  = (const float*)d_in[8];
    const float* wfc   = (const float*)d_in[9];
    const float* bfc   = (const float*)d_in[10];
    const float* wmlp  = (const float*)d_in[11];
    const float* bmlp  = (const float*)d_in[12];
    float* out = (float*)d_out;

    int tokens = in_sizes[0] / D;   // 8192
    int B = tokens / SEQ;

    float *xln, *qkvb, *attnb, *resb, *mlnb, *fcb;
    float *wattn_t, *wproj_t, *wfc_t, *wmlp_t;
    cudaGetSymbolAddress((void**)&xln,   g_xln);
    cudaGetSymbolAddress((void**)&qkvb,  g_qkv);
    cudaGetSymbolAddress((void**)&attnb, g_attn);
    cudaGetSymbolAddress((void**)&resb,  g_res);
    cudaGetSymbolAddress((void**)&mlnb,  g_mln);
    cudaGetSymbolAddress((void**)&fcb,   g_fc);
    cudaGetSymbolAddress((void**)&wattn_t, g_wattn_t);
    cudaGetSymbolAddress((void**)&wproj_t, g_wproj_t);
    cudaGetSymbolAddress((void**)&wfc_t,   g_wfc_t);
    cudaGetSymbolAddress((void**)&wmlp_t,  g_wmlp_t);

    cudaFuncSetAttribute(tc_gemm<0>, cudaFuncAttributeMaxDynamicSharedMemorySize, GSMEM);
    cudaFuncSetAttribute(tc_gemm<1>, cudaFuncAttributeMaxDynamicSharedMemorySize, GSMEM);
    cudaFuncSetAttribute(tc_gemm<2>, cudaFuncAttributeMaxDynamicSharedMemorySize, GSMEM);
    cudaFuncSetAttribute(attn_kernel, cudaFuncAttributeMaxDynamicSharedMemorySize, ASMEM);

    // weight transposes (Bt[N][K] K-major, tf32-rounded)
    transpose_kernel<<<dim3(3 * D / 32, D / 32), 256>>>(wattn, wattn_t, D, 3 * D);
    transpose_kernel<<<dim3(D / 32, D / 32), 256>>>(wproj, wproj_t, D, D);
    transpose_kernel<<<dim3(FF / 32, D / 32), 256>>>(wfc, wfc_t, D, FF);
    transpose_kernel<<<dim3(D / 32, FF / 32), 256>>>(wmlp, wmlp_t, FF, D);

    // LN1
    ln_kernel<<<tokens, 256>>>(hs, ln1g, ln1b, xln);

    // QKV = xln @ w_attn + b_attn
    tc_gemm<0><<<dim3(3 * D / BN, tokens / BM), 128, GSMEM>>>(
        xln, wattn_t, battn, nullptr, qkvb, tokens, 3 * D, D);

    // attention (tf32 mma flash attention)
    attn_kernel<<<dim3(SEQ / 128, H, B), 128, ASMEM>>>(qkvb, attnb);

    // resid = hs + attnb @ w_attn_proj + b_attn_proj
    tc_gemm<2><<<dim3(D / BN, tokens / BM), 128, GSMEM>>>(
        attnb, wproj_t, bproj, hs, resb, tokens, D, D);

    // LN2
    ln_kernel<<<tokens, 256>>>(resb, ln2g, ln2b, mlnb);

    // fc = gelu_new(mlnb @ w_fc + b_fc)
    tc_gemm<1><<<dim3(FF / BN, tokens / BM), 128, GSMEM>>>(
        mlnb, wfc_t, bfc, nullptr, fcb, tokens, FF, D);

    // out = resb + fcb @ w_mlp_proj + b_mlp_proj
    tc_gemm<2><<<dim3(D / BN, tokens / BM), 128, GSMEM>>>(
        fcb, wmlp_t, bmlp, resb, out, tokens, D, FF);
}